// round 6
// baseline (speedup 1.0000x reference)
#include <cuda_runtime.h>

// Problem constants
#define BB    8
#define SEQ   1024
#define CD    768
#define NH    12
#define HD    64
#define MTOT  (BB * SEQ)        // 8192
#define QKVN  (3 * CD)          // 2304
#define SCALE 0.125f            // hd^-0.5
#define QUADC 5.0f

// Scratch (device globals — no allocation allowed)
__device__ float g_q[BB * NH * SEQ * HD];
__device__ float g_k[BB * NH * SEQ * HD];
__device__ float g_v[BB * NH * SEQ * HD];
__device__ float g_att[MTOT * CD];   // [B, N, C] layout (C = h*64 + d)

// ---------------------------------------------------------------------------
// Tiled GEMM  C = A @ B^T   (A: [M,K] row-major, B: [N,K] row-major)
// BM=BN=64, BK=16, 256 threads, 4x4 microtile per thread.
// MODE 0: scatter epilogue into g_q/g_k/g_v ([B,H,N,hd])
// MODE 1: dense epilogue with bias into out ([M,N])
// ---------------------------------------------------------------------------
template <int MODE>
__global__ void gemm_abt_kernel(const float* __restrict__ A,
                                const float* __restrict__ B,
                                float* __restrict__ Cout,
                                const float* __restrict__ bias,
                                int M, int N, int K) {
    __shared__ float As[16][64];
    __shared__ float Bs[16][64];

    const int bm = blockIdx.y * 64;
    const int bn = blockIdx.x * 64;
    const int t  = threadIdx.x;
    const int ty = t >> 4;       // 0..15
    const int tx = t & 15;       // 0..15

    const int lr  = t >> 2;      // 0..63  (load row)
    const int lc4 = (t & 3) * 4; // 0,4,8,12 (load col group)

    float acc[4][4];
#pragma unroll
    for (int i = 0; i < 4; i++)
#pragma unroll
        for (int j = 0; j < 4; j++) acc[i][j] = 0.0f;

    for (int k0 = 0; k0 < K; k0 += 16) {
        float4 a4 = *(const float4*)&A[(size_t)(bm + lr) * K + k0 + lc4];
        float4 b4 = *(const float4*)&B[(size_t)(bn + lr) * K + k0 + lc4];
        As[lc4 + 0][lr] = a4.x; As[lc4 + 1][lr] = a4.y;
        As[lc4 + 2][lr] = a4.z; As[lc4 + 3][lr] = a4.w;
        Bs[lc4 + 0][lr] = b4.x; Bs[lc4 + 1][lr] = b4.y;
        Bs[lc4 + 2][lr] = b4.z; Bs[lc4 + 3][lr] = b4.w;
        __syncthreads();

#pragma unroll
        for (int kk = 0; kk < 16; kk++) {
            float4 av = *(const float4*)&As[kk][ty * 4];
            float4 bv = *(const float4*)&Bs[kk][tx * 4];
            acc[0][0] += av.x * bv.x; acc[0][1] += av.x * bv.y;
            acc[0][2] += av.x * bv.z; acc[0][3] += av.x * bv.w;
            acc[1][0] += av.y * bv.x; acc[1][1] += av.y * bv.y;
            acc[1][2] += av.y * bv.z; acc[1][3] += av.y * bv.w;
            acc[2][0] += av.z * bv.x; acc[2][1] += av.z * bv.y;
            acc[2][2] += av.z * bv.z; acc[2][3] += av.z * bv.w;
            acc[3][0] += av.w * bv.x; acc[3][1] += av.w * bv.y;
            acc[3][2] += av.w * bv.z; acc[3][3] += av.w * bv.w;
        }
        __syncthreads();
    }

    if (MODE == 0) {
        // qkv scatter: col j of the 2304-wide output -> (s, h, d).
        // A 64-wide tile at bn lies entirely inside one s and one h.
        const int s = bn / CD;
        const int h = (bn % CD) / HD;
        float* dst = (s == 0) ? g_q : (s == 1) ? g_k : g_v;
        const int dcol = tx * 4;   // bn % 64 == 0 always
#pragma unroll
        for (int i = 0; i < 4; i++) {
            const int gm = bm + ty * 4 + i;
            const int b  = gm >> 10;
            const int n  = gm & 1023;
            float4 o = make_float4(acc[i][0], acc[i][1], acc[i][2], acc[i][3]);
            *(float4*)&dst[((size_t)(b * NH + h) * SEQ + n) * HD + dcol] = o;
        }
    } else {
        const int gn = bn + tx * 4;
        float4 bv4 = *(const float4*)&bias[gn];
#pragma unroll
        for (int i = 0; i < 4; i++) {
            const int gm = bm + ty * 4 + i;
            float4 o = make_float4(acc[i][0] + bv4.x, acc[i][1] + bv4.y,
                                   acc[i][2] + bv4.z, acc[i][3] + bv4.w);
            *(float4*)&Cout[(size_t)gm * N + gn] = o;
        }
    }
}

// ---------------------------------------------------------------------------
// Quad2 attention: per (b,h), 64-row Q tiles, streaming 32-row KV tiles.
// t = (s*scale + 5)^2 >= 0  => single pass: acc += t*V, den += t, out = acc/den
// ---------------------------------------------------------------------------
__global__ void attn_kernel() {
    __shared__ float Qs[64][64];       // [r][d], float4 reads, broadcast-safe
    __shared__ float Kst[64][34];      // [d][m] transposed, float2 reads
    __shared__ float Vs[32][64];       // [m][d], float4 reads
    __shared__ float Ss[64][36];       // [r][m] scores, float4 reads
    __shared__ float den_s[64];

    const int bh = blockIdx.y;             // b*NH + h
    const int r0 = blockIdx.x * 64;
    const float* qp = g_q + (size_t)bh * SEQ * HD;
    const float* kp = g_k + (size_t)bh * SEQ * HD;
    const float* vp = g_v + (size_t)bh * SEQ * HD;

    const int t  = threadIdx.x;
    const int ty = t >> 4, tx = t & 15;
    const int ty4 = ty * 4, tx4 = tx * 4, tx2 = tx * 2;

    // Load Q tile (64x64): coalesced float4
    {
        const int r  = t >> 2;
        const int c0 = (t & 3) * 16;
#pragma unroll
        for (int u = 0; u < 4; u++) {
            *(float4*)&Qs[r][c0 + u * 4] =
                *(const float4*)&qp[(size_t)(r0 + r) * HD + c0 + u * 4];
        }
    }

    float acc[4][4];
    float den[4] = {0.f, 0.f, 0.f, 0.f};
#pragma unroll
    for (int i = 0; i < 4; i++)
#pragma unroll
        for (int j = 0; j < 4; j++) acc[i][j] = 0.0f;

    for (int m0 = 0; m0 < SEQ; m0 += 32) {
        __syncthreads();   // guard Kst/Vs/Ss reuse (and Q readiness on iter 0)
        // Load K transposed + V (coalesced global reads)
        {
            const int m  = t >> 3;        // 0..31
            const int dg = (t & 7) * 8;   // 0..56
#pragma unroll
            for (int u = 0; u < 8; u++)
                Kst[dg + u][m] = kp[(size_t)(m0 + m) * HD + dg + u];
#pragma unroll
            for (int u = 0; u < 2; u++)
                *(float4*)&Vs[m][dg + u * 4] =
                    *(const float4*)&vp[(size_t)(m0 + m) * HD + dg + u * 4];
        }
        __syncthreads();

        // Phase A: scores S[64][32] = Q @ K^T, quad2 transform into Ss
        float sacc[4][2] = {{0.f,0.f},{0.f,0.f},{0.f,0.f},{0.f,0.f}};
#pragma unroll
        for (int d0 = 0; d0 < 64; d0 += 4) {
            float qv[4][4];
#pragma unroll
            for (int i = 0; i < 4; i++)
                *(float4*)qv[i] = *(const float4*)&Qs[ty4 + i][d0];
            float kx[4], ky[4];
#pragma unroll
            for (int u = 0; u < 4; u++) {
                float2 k2 = *(const float2*)&Kst[d0 + u][tx2];
                kx[u] = k2.x; ky[u] = k2.y;
            }
#pragma unroll
            for (int u = 0; u < 4; u++)
#pragma unroll
                for (int i = 0; i < 4; i++) {
                    sacc[i][0] += qv[i][u] * kx[u];
                    sacc[i][1] += qv[i][u] * ky[u];
                }
        }
#pragma unroll
        for (int i = 0; i < 4; i++)
#pragma unroll
            for (int j = 0; j < 2; j++) {
                float s = sacc[i][j] * SCALE + QUADC;
                Ss[ty4 + i][tx2 + j] = s * s;
            }
        __syncthreads();

        // Phase B: acc += Ss @ Vs ; den += rowsum(Ss) (on tx==0 threads)
#pragma unroll
        for (int mm = 0; mm < 32; mm += 4) {
            float vv[4][4], sv[4][4];
#pragma unroll
            for (int u = 0; u < 4; u++)
                *(float4*)vv[u] = *(const float4*)&Vs[mm + u][tx4];
#pragma unroll
            for (int i = 0; i < 4; i++)
                *(float4*)sv[i] = *(const float4*)&Ss[ty4 + i][mm];
#pragma unroll
            for (int i = 0; i < 4; i++) {
#pragma unroll
                for (int u = 0; u < 4; u++) {
                    acc[i][0] += sv[i][u] * vv[u][0];
                    acc[i][1] += sv[i][u] * vv[u][1];
                    acc[i][2] += sv[i][u] * vv[u][2];
                    acc[i][3] += sv[i][u] * vv[u][3];
                }
                if (tx == 0)
                    den[i] += sv[i][0] + sv[i][1] + sv[i][2] + sv[i][3];
            }
        }
    }

    __syncthreads();
    if (tx == 0) {
#pragma unroll
        for (int i = 0; i < 4; i++) den_s[ty4 + i] = den[i];
    }
    __syncthreads();

    const int b = bh / NH;
    const int h = bh % NH;
#pragma unroll
    for (int i = 0; i < 4; i++) {
        const float inv = 1.0f / den_s[ty4 + i];
        float4 o = make_float4(acc[i][0] * inv, acc[i][1] * inv,
                               acc[i][2] * inv, acc[i][3] * inv);
        *(float4*)&g_att[((size_t)(b * SEQ + r0 + ty4 + i)) * CD + h * HD + tx4] = o;
    }
}

// ---------------------------------------------------------------------------
extern "C" void kernel_launch(void* const* d_in, const int* in_sizes, int n_in,
                              void* d_out, int out_size) {
    // Bind inputs by element count (robust to metadata ordering):
    //   x: 8*1024*768 = 6291456, qkv_w: 2304*768 = 1769472,
    //   proj_w: 768*768 = 589824, proj_b: 768
    const float* x = nullptr;
    const float* qkv_w = nullptr;
    const float* proj_w = nullptr;
    const float* proj_b = nullptr;
    for (int i = 0; i < n_in; i++) {
        switch (in_sizes[i]) {
            case MTOT * CD:  x      = (const float*)d_in[i]; break;
            case QKVN * CD:  qkv_w  = (const float*)d_in[i]; break;
            case CD * CD:    proj_w = (const float*)d_in[i]; break;
            case CD:         proj_b = (const float*)d_in[i]; break;
            default: break;
        }
    }
    float* out = (float*)d_out;

    // Resolve the DEVICE address of g_att (passing a __device__ symbol
    // directly as a kernel argument from host code yields the host shadow
    // address — that was the R4 bug). Pure query: graph-capture safe.
    float* att_ptr = nullptr;
    cudaGetSymbolAddress((void**)&att_ptr, g_att);

    dim3 blk(256);

    // 1) qkv projection, scattered into g_q/g_k/g_v (written via device symbols)
    gemm_abt_kernel<0><<<dim3(QKVN / 64, MTOT / 64), blk>>>(
        x, qkv_w, nullptr, nullptr, MTOT, QKVN, CD);

    // 2) quad2 attention -> g_att ([B,N,C])
    attn_kernel<<<dim3(SEQ / 64, BB * NH), blk>>>();

    // 3) output projection + bias (A = device address of g_att)
    gemm_abt_kernel<1><<<dim3(CD / 64, MTOT / 64), blk>>>(
        att_ptr, proj_w, out, proj_b, MTOT, CD, CD);
}

// round 9
// speedup vs baseline: 1.5214x; 1.5214x over previous
#include <cuda_runtime.h>
#include <cuda_bf16.h>
#include <cstdint>

// ---------------------------------------------------------------------------
// Problem constants
// ---------------------------------------------------------------------------
#define BB    8
#define SEQ   1024
#define CD    768
#define NH    12
#define HD    64
#define MTOT  (BB * SEQ)        // 8192
#define QKVN  (3 * CD)          // 2304
#define SCALE 0.125f
#define QUADC 5.0f

// ---------------------------------------------------------------------------
// Scratch (device globals — no allocation allowed)
// ---------------------------------------------------------------------------
__device__ float g_q[BB * NH * SEQ * HD];
__device__ float g_k[BB * NH * SEQ * HD];
__device__ float g_v[BB * NH * SEQ * HD];
__device__ __nv_bfloat16 g_xh[MTOT * CD];
__device__ __nv_bfloat16 g_xl[MTOT * CD];
__device__ __nv_bfloat16 g_wh[QKVN * CD];
__device__ __nv_bfloat16 g_wl[QKVN * CD];
__device__ __nv_bfloat16 g_ph[CD * CD];
__device__ __nv_bfloat16 g_pl[CD * CD];
__device__ __nv_bfloat16 g_ath[MTOT * CD];   // attention out hi ([B,N,C])
__device__ __nv_bfloat16 g_atl[MTOT * CD];   // attention out lo

// ---------------------------------------------------------------------------
// mma.sync m16n8k16 bf16 (sm_80+ instruction — compiles at compute_103 base;
// tcgen05 does NOT, the harness's PTX stage targets plain sm_103: R7 failure)
// ---------------------------------------------------------------------------
__device__ __forceinline__ void mma16816(float* d, const uint32_t* a,
                                         const uint32_t* b) {
    asm volatile(
        "mma.sync.aligned.m16n8k16.row.col.f32.bf16.bf16.f32 "
        "{%0,%1,%2,%3}, {%4,%5,%6,%7}, {%8,%9}, {%0,%1,%2,%3};"
        : "+f"(d[0]), "+f"(d[1]), "+f"(d[2]), "+f"(d[3])
        : "r"(a[0]), "r"(a[1]), "r"(a[2]), "r"(a[3]),
          "r"(b[0]), "r"(b[1]));
}

// ---------------------------------------------------------------------------
// fp32 -> bf16 hi/lo split (elementwise)
// ---------------------------------------------------------------------------
__global__ void split_kernel(const float* __restrict__ src,
                             __nv_bfloat16* __restrict__ dh,
                             __nv_bfloat16* __restrict__ dl, int n) {
    int i = (blockIdx.x * 256 + threadIdx.x) * 4;
    if (i >= n) return;
    float4 v = *(const float4*)&src[i];
    float  f[4] = {v.x, v.y, v.z, v.w};
    __nv_bfloat16 h[4], l[4];
#pragma unroll
    for (int u = 0; u < 4; u++) {
        h[u] = __float2bfloat16(f[u]);
        l[u] = __float2bfloat16(f[u] - __bfloat162float(h[u]));
    }
    *(__nv_bfloat162*)&dh[i]     = __nv_bfloat162(h[0], h[1]);
    *(__nv_bfloat162*)&dh[i + 2] = __nv_bfloat162(h[2], h[3]);
    *(__nv_bfloat162*)&dl[i]     = __nv_bfloat162(l[0], l[1]);
    *(__nv_bfloat162*)&dl[i + 2] = __nv_bfloat162(l[2], l[3]);
}

// ---------------------------------------------------------------------------
// Tensor-core GEMM:  C[M,N] = A[M,768] @ B[N,768]^T  (bf16 hi/lo, fp32 accum)
// CTA 128x128, BK=32, 256 threads = 8 warps, warp tile 64x32 (4 x m16, 4 x n8)
// SMEM row stride 40 bf16 (20 words) => conflict-free fragment LDS.
// MODE 0: scatter into g_q/g_k/g_v   MODE 1: dense + bias into Cout
// ---------------------------------------------------------------------------
#define TSTRIDE 40

template <int MODE>
__global__ __launch_bounds__(256)
void tc_gemm_kernel(const __nv_bfloat16* __restrict__ Ah,
                    const __nv_bfloat16* __restrict__ Al,
                    const __nv_bfloat16* __restrict__ Bh,
                    const __nv_bfloat16* __restrict__ Bl,
                    float* __restrict__ Cout,
                    const float* __restrict__ bias) {
    __shared__ __nv_bfloat16 AsH[128][TSTRIDE];
    __shared__ __nv_bfloat16 AsL[128][TSTRIDE];
    __shared__ __nv_bfloat16 BsH[128][TSTRIDE];
    __shared__ __nv_bfloat16 BsL[128][TSTRIDE];

    const int t    = threadIdx.x;
    const int wid  = t >> 5;
    const int lane = t & 31;
    const int bm   = blockIdx.y * 128;
    const int bn   = blockIdx.x * 128;

    const int warp_m = wid & 1;        // 0..1  (64-row halves)
    const int warp_n = wid >> 1;       // 0..3  (32-col quarters)
    const int r   = lane >> 2;         // 0..7
    const int c2  = (lane & 3) * 2;    // 0,2,4,6

    float acc[4][4][4];
#pragma unroll
    for (int f = 0; f < 4; f++)
#pragma unroll
        for (int g = 0; g < 4; g++)
#pragma unroll
            for (int u = 0; u < 4; u++) acc[f][g][u] = 0.0f;

    for (int k0 = 0; k0 < CD; k0 += 32) {
        __syncthreads();
        // Load 4 tiles: 128 rows x 32 bf16 each = 512 uint4 chunks per tile.
#pragma unroll
        for (int i = 0; i < 2; i++) {
            const int idx = t + 256 * i;      // 0..511
            const int row = idx >> 2;         // 0..127
            const int ch  = idx & 3;          // 0..3 (8 bf16 each)
            const size_t ga = (size_t)(bm + row) * CD + k0 + ch * 8;
            const size_t gb = (size_t)(bn + row) * CD + k0 + ch * 8;
            *(uint4*)&AsH[row][ch * 8] = *(const uint4*)&Ah[ga];
            *(uint4*)&AsL[row][ch * 8] = *(const uint4*)&Al[ga];
            *(uint4*)&BsH[row][ch * 8] = *(const uint4*)&Bh[gb];
            *(uint4*)&BsL[row][ch * 8] = *(const uint4*)&Bl[gb];
        }
        __syncthreads();

#pragma unroll
        for (int s = 0; s < 2; s++) {
            const int kb = s * 16;
            uint32_t aH[4][4], aL[4][4], bH[4][2], bL[4][2];
#pragma unroll
            for (int f = 0; f < 4; f++) {
                const int m0 = warp_m * 64 + f * 16 + r;
                aH[f][0] = *(const uint32_t*)&AsH[m0    ][kb + c2];
                aH[f][1] = *(const uint32_t*)&AsH[m0 + 8][kb + c2];
                aH[f][2] = *(const uint32_t*)&AsH[m0    ][kb + 8 + c2];
                aH[f][3] = *(const uint32_t*)&AsH[m0 + 8][kb + 8 + c2];
                aL[f][0] = *(const uint32_t*)&AsL[m0    ][kb + c2];
                aL[f][1] = *(const uint32_t*)&AsL[m0 + 8][kb + c2];
                aL[f][2] = *(const uint32_t*)&AsL[m0    ][kb + 8 + c2];
                aL[f][3] = *(const uint32_t*)&AsL[m0 + 8][kb + 8 + c2];
            }
#pragma unroll
            for (int g = 0; g < 4; g++) {
                const int n0 = warp_n * 32 + g * 8 + r;
                bH[g][0] = *(const uint32_t*)&BsH[n0][kb + c2];
                bH[g][1] = *(const uint32_t*)&BsH[n0][kb + 8 + c2];
                bL[g][0] = *(const uint32_t*)&BsL[n0][kb + c2];
                bL[g][1] = *(const uint32_t*)&BsL[n0][kb + 8 + c2];
            }
#pragma unroll
            for (int f = 0; f < 4; f++)
#pragma unroll
                for (int g = 0; g < 4; g++) {
                    mma16816(acc[f][g], aH[f], bH[g]);
                    mma16816(acc[f][g], aH[f], bL[g]);
                    mma16816(acc[f][g], aL[f], bH[g]);
                }
        }
    }

    // Epilogue. Fragment c0={row, col}, c1={row, col+1}, c2/c3 at row+8.
#pragma unroll
    for (int f = 0; f < 4; f++) {
        const int gm0 = bm + warp_m * 64 + f * 16 + r;
#pragma unroll
        for (int g = 0; g < 4; g++) {
            const int gc = bn + warp_n * 32 + g * 8 + c2;
            if (MODE == 0) {
                const int s = gc / CD;               // 0,1,2 -> q,k,v
                const int h = (gc % CD) / HD;
                const int d = gc % HD;               // even
                float* dst = (s == 0) ? g_q : (s == 1) ? g_k : g_v;
#pragma unroll
                for (int hrow = 0; hrow < 2; hrow++) {
                    const int gm = gm0 + hrow * 8;
                    const int b  = gm >> 10;
                    const int n  = gm & 1023;
                    float2 o = make_float2(acc[f][g][hrow * 2],
                                           acc[f][g][hrow * 2 + 1]);
                    *(float2*)&dst[((size_t)(b * NH + h) * SEQ + n) * HD + d] = o;
                }
            } else {
                const float b0 = bias[gc], b1 = bias[gc + 1];
#pragma unroll
                for (int hrow = 0; hrow < 2; hrow++) {
                    const int gm = gm0 + hrow * 8;
                    float2 o = make_float2(acc[f][g][hrow * 2] + b0,
                                           acc[f][g][hrow * 2 + 1] + b1);
                    *(float2*)&Cout[(size_t)gm * CD + gc] = o;
                }
            }
        }
    }
}

// ---------------------------------------------------------------------------
// Quad2 attention (SIMT fp32) — epilogue writes bf16 hi/lo for proj GEMM
// ---------------------------------------------------------------------------
__global__ void attn_kernel() {
    __shared__ float Qs[64][64];
    __shared__ float Kst[64][34];
    __shared__ float Vs[32][64];
    __shared__ float Ss[64][36];
    __shared__ float den_s[64];

    const int bh = blockIdx.y;
    const int r0 = blockIdx.x * 64;
    const float* qp = g_q + (size_t)bh * SEQ * HD;
    const float* kp = g_k + (size_t)bh * SEQ * HD;
    const float* vp = g_v + (size_t)bh * SEQ * HD;

    const int t  = threadIdx.x;
    const int ty = t >> 4, tx = t & 15;
    const int ty4 = ty * 4, tx4 = tx * 4, tx2 = tx * 2;

    {
        const int r  = t >> 2;
        const int c0 = (t & 3) * 16;
#pragma unroll
        for (int u = 0; u < 4; u++)
            *(float4*)&Qs[r][c0 + u * 4] =
                *(const float4*)&qp[(size_t)(r0 + r) * HD + c0 + u * 4];
    }

    float acc[4][4];
    float den[4] = {0.f, 0.f, 0.f, 0.f};
#pragma unroll
    for (int i = 0; i < 4; i++)
#pragma unroll
        for (int j = 0; j < 4; j++) acc[i][j] = 0.0f;

    for (int m0 = 0; m0 < SEQ; m0 += 32) {
        __syncthreads();
        {
            const int m  = t >> 3;
            const int dg = (t & 7) * 8;
#pragma unroll
            for (int u = 0; u < 8; u++)
                Kst[dg + u][m] = kp[(size_t)(m0 + m) * HD + dg + u];
#pragma unroll
            for (int u = 0; u < 2; u++)
                *(float4*)&Vs[m][dg + u * 4] =
                    *(const float4*)&vp[(size_t)(m0 + m) * HD + dg + u * 4];
        }
        __syncthreads();

        float sacc[4][2] = {{0.f,0.f},{0.f,0.f},{0.f,0.f},{0.f,0.f}};
#pragma unroll
        for (int d0 = 0; d0 < 64; d0 += 4) {
            float qv[4][4];
#pragma unroll
            for (int i = 0; i < 4; i++)
                *(float4*)qv[i] = *(const float4*)&Qs[ty4 + i][d0];
            float kx[4], ky[4];
#pragma unroll
            for (int u = 0; u < 4; u++) {
                float2 k2 = *(const float2*)&Kst[d0 + u][tx2];
                kx[u] = k2.x; ky[u] = k2.y;
            }
#pragma unroll
            for (int u = 0; u < 4; u++)
#pragma unroll
                for (int i = 0; i < 4; i++) {
                    sacc[i][0] += qv[i][u] * kx[u];
                    sacc[i][1] += qv[i][u] * ky[u];
                }
        }
#pragma unroll
        for (int i = 0; i < 4; i++)
#pragma unroll
            for (int j = 0; j < 2; j++) {
                float s = sacc[i][j] * SCALE + QUADC;
                Ss[ty4 + i][tx2 + j] = s * s;
            }
        __syncthreads();

#pragma unroll
        for (int mm = 0; mm < 32; mm += 4) {
            float vv[4][4], sv[4][4];
#pragma unroll
            for (int u = 0; u < 4; u++)
                *(float4*)vv[u] = *(const float4*)&Vs[mm + u][tx4];
#pragma unroll
            for (int i = 0; i < 4; i++)
                *(float4*)sv[i] = *(const float4*)&Ss[ty4 + i][mm];
#pragma unroll
            for (int i = 0; i < 4; i++) {
#pragma unroll
                for (int u = 0; u < 4; u++) {
                    acc[i][0] += sv[i][u] * vv[u][0];
                    acc[i][1] += sv[i][u] * vv[u][1];
                    acc[i][2] += sv[i][u] * vv[u][2];
                    acc[i][3] += sv[i][u] * vv[u][3];
                }
                if (tx == 0)
                    den[i] += sv[i][0] + sv[i][1] + sv[i][2] + sv[i][3];
            }
        }
    }

    __syncthreads();
    if (tx == 0) {
#pragma unroll
        for (int i = 0; i < 4; i++) den_s[ty4 + i] = den[i];
    }
    __syncthreads();

    const int b = bh / NH;
    const int h = bh % NH;
#pragma unroll
    for (int i = 0; i < 4; i++) {
        const float inv = 1.0f / den_s[ty4 + i];
        const size_t base =
            ((size_t)(b * SEQ + r0 + ty4 + i)) * CD + h * HD + tx4;
        __nv_bfloat16 hh[4], ll[4];
#pragma unroll
        for (int u = 0; u < 4; u++) {
            const float o = acc[i][u] * inv;
            hh[u] = __float2bfloat16(o);
            ll[u] = __float2bfloat16(o - __bfloat162float(hh[u]));
        }
        *(__nv_bfloat162*)&g_ath[base]     = __nv_bfloat162(hh[0], hh[1]);
        *(__nv_bfloat162*)&g_ath[base + 2] = __nv_bfloat162(hh[2], hh[3]);
        *(__nv_bfloat162*)&g_atl[base]     = __nv_bfloat162(ll[0], ll[1]);
        *(__nv_bfloat162*)&g_atl[base + 2] = __nv_bfloat162(ll[2], ll[3]);
    }
}

// ---------------------------------------------------------------------------
extern "C" void kernel_launch(void* const* d_in, const int* in_sizes, int n_in,
                              void* d_out, int out_size) {
    const float* x = nullptr;
    const float* qkv_w = nullptr;
    const float* proj_w = nullptr;
    const float* proj_b = nullptr;
    for (int i = 0; i < n_in; i++) {
        switch (in_sizes[i]) {
            case MTOT * CD: x      = (const float*)d_in[i]; break;
            case QKVN * CD: qkv_w  = (const float*)d_in[i]; break;
            case CD * CD:   proj_w = (const float*)d_in[i]; break;
            case CD:        proj_b = (const float*)d_in[i]; break;
            default: break;
        }
    }
    float* out = (float*)d_out;

    // Device addresses of __device__ symbols (host shadow addr = R4 trap)
    __nv_bfloat16 *xh, *xl, *wh, *wl, *ph, *pl, *ath, *atl;
    cudaGetSymbolAddress((void**)&xh,  g_xh);
    cudaGetSymbolAddress((void**)&xl,  g_xl);
    cudaGetSymbolAddress((void**)&wh,  g_wh);
    cudaGetSymbolAddress((void**)&wl,  g_wl);
    cudaGetSymbolAddress((void**)&ph,  g_ph);
    cudaGetSymbolAddress((void**)&pl,  g_pl);
    cudaGetSymbolAddress((void**)&ath, g_ath);
    cudaGetSymbolAddress((void**)&atl, g_atl);

    // 0) split fp32 inputs into bf16 hi/lo
    split_kernel<<<(MTOT * CD) / (256 * 4), 256>>>(x, xh, xl, MTOT * CD);
    split_kernel<<<(QKVN * CD) / (256 * 4), 256>>>(qkv_w, wh, wl, QKVN * CD);
    split_kernel<<<(CD * CD)   / (256 * 4), 256>>>(proj_w, ph, pl, CD * CD);

    // 1) qkv projection (tensor cores) -> g_q/g_k/g_v
    tc_gemm_kernel<0><<<dim3(QKVN / 128, MTOT / 128), 256>>>(
        xh, xl, wh, wl, nullptr, nullptr);

    // 2) quad2 attention -> g_ath/g_atl
    attn_kernel<<<dim3(SEQ / 64, BB * NH), 256>>>();

    // 3) output projection + bias (tensor cores)
    tc_gemm_kernel<1><<<dim3(CD / 128, MTOT / 128), 256>>>(
        ath, atl, ph, pl, out, proj_b);
}

// round 12
// speedup vs baseline: 2.5235x; 1.6587x over previous
#include <cuda_runtime.h>
#include <cuda_bf16.h>
#include <cstdint>

// ---------------------------------------------------------------------------
// Problem constants
// ---------------------------------------------------------------------------
#define BB    8
#define SEQ   1024
#define CD    768
#define NH    12
#define HD    64
#define MTOT  (BB * SEQ)        // 8192
#define QKVN  (3 * CD)          // 2304
#define SCALE 0.125f
#define QUADC 5.0f

// ---------------------------------------------------------------------------
// Scratch (device globals — no allocation allowed)
// ---------------------------------------------------------------------------
__device__ __nv_bfloat16 g_qh[BB * NH * SEQ * HD];
__device__ __nv_bfloat16 g_ql[BB * NH * SEQ * HD];
__device__ __nv_bfloat16 g_kh[BB * NH * SEQ * HD];
__device__ __nv_bfloat16 g_kl[BB * NH * SEQ * HD];
__device__ __nv_bfloat16 g_vh[BB * NH * SEQ * HD];
__device__ __nv_bfloat16 g_vl[BB * NH * SEQ * HD];
__device__ __nv_bfloat16 g_xh[MTOT * CD];
__device__ __nv_bfloat16 g_xl[MTOT * CD];
__device__ __nv_bfloat16 g_wh[QKVN * CD];
__device__ __nv_bfloat16 g_wl[QKVN * CD];
__device__ __nv_bfloat16 g_ph[CD * CD];
__device__ __nv_bfloat16 g_pl[CD * CD];
__device__ __nv_bfloat16 g_ath[MTOT * CD];   // attention out hi ([B,N,C])
__device__ __nv_bfloat16 g_atl[MTOT * CD];   // attention out lo

// ---------------------------------------------------------------------------
// mma.sync m16n8k16 bf16 (sm_80+; tcgen05 PTX rejected at compute_103 — R7)
// Frag maps (verified by passing GEMM): A a0=(r,k0) a1=(r+8,k0) a2=(r,k0+8)
// a3=(r+8,k0+8); B b0=(n=r,k0) b1=(n=r,k0+8); C c0=(r,2c) c1=(r,2c+1)
// c2=(r+8,2c) c3=(r+8,2c+1), with r=lane>>2, c=lane&3.
// ---------------------------------------------------------------------------
__device__ __forceinline__ void mma16816(float* d, const uint32_t* a,
                                         const uint32_t* b) {
    asm volatile(
        "mma.sync.aligned.m16n8k16.row.col.f32.bf16.bf16.f32 "
        "{%0,%1,%2,%3}, {%4,%5,%6,%7}, {%8,%9}, {%0,%1,%2,%3};"
        : "+f"(d[0]), "+f"(d[1]), "+f"(d[2]), "+f"(d[3])
        : "r"(a[0]), "r"(a[1]), "r"(a[2]), "r"(a[3]),
          "r"(b[0]), "r"(b[1]));
}

__device__ __forceinline__ void ldmx4t(uint32_t* d, uint32_t addr) {
    asm volatile(
        "ldmatrix.sync.aligned.m8n8.x4.trans.shared.b16 {%0,%1,%2,%3}, [%4];"
        : "=r"(d[0]), "=r"(d[1]), "=r"(d[2]), "=r"(d[3]) : "r"(addr));
}

__device__ __forceinline__ uint32_t smem_u32(const void* p) {
    uint32_t a;
    asm("{ .reg .u64 t; cvta.to.shared.u64 t, %1; cvt.u32.u64 %0, t; }"
        : "=r"(a) : "l"(p));
    return a;
}

// split two fp32 into packed bf16x2 hi + bf16x2 lo (low half = first element)
__device__ __forceinline__ void split2(float x, float y,
                                       uint32_t& hi, uint32_t& lo) {
    __nv_bfloat16 hx = __float2bfloat16(x);
    __nv_bfloat16 hy = __float2bfloat16(y);
    __nv_bfloat16 lx = __float2bfloat16(x - __bfloat162float(hx));
    __nv_bfloat16 ly = __float2bfloat16(y - __bfloat162float(hy));
    hi = ((uint32_t)__bfloat16_as_ushort(hy) << 16) |
         (uint32_t)__bfloat16_as_ushort(hx);
    lo = ((uint32_t)__bfloat16_as_ushort(ly) << 16) |
         (uint32_t)__bfloat16_as_ushort(lx);
}

// ---------------------------------------------------------------------------
// fp32 -> bf16 hi/lo split (elementwise)
// ---------------------------------------------------------------------------
__global__ void split_kernel(const float* __restrict__ src,
                             __nv_bfloat16* __restrict__ dh,
                             __nv_bfloat16* __restrict__ dl, int n) {
    int i = (blockIdx.x * 256 + threadIdx.x) * 4;
    if (i >= n) return;
    float4 v = *(const float4*)&src[i];
    float  f[4] = {v.x, v.y, v.z, v.w};
    uint32_t h01, l01, h23, l23;
    split2(f[0], f[1], h01, l01);
    split2(f[2], f[3], h23, l23);
    *(uint32_t*)&dh[i]     = h01;  *(uint32_t*)&dh[i + 2] = h23;
    *(uint32_t*)&dl[i]     = l01;  *(uint32_t*)&dl[i + 2] = l23;
}

// ---------------------------------------------------------------------------
// Tensor-core GEMM:  C[M,N] = A[M,768] @ B[N,768]^T  (bf16 hi/lo, fp32 accum)
// CTA 128x128, BK=32, 256 threads = 8 warps, warp tile 64x32.
// MODE 0: scatter bf16 hi/lo into g_q*/g_k*/g_v*   MODE 1: fp32 + bias
// ---------------------------------------------------------------------------
#define TSTRIDE 40

template <int MODE>
__global__ __launch_bounds__(256)
void tc_gemm_kernel(const __nv_bfloat16* __restrict__ Ah,
                    const __nv_bfloat16* __restrict__ Al,
                    const __nv_bfloat16* __restrict__ Bh,
                    const __nv_bfloat16* __restrict__ Bl,
                    float* __restrict__ Cout,
                    const float* __restrict__ bias) {
    __shared__ __nv_bfloat16 AsH[128][TSTRIDE];
    __shared__ __nv_bfloat16 AsL[128][TSTRIDE];
    __shared__ __nv_bfloat16 BsH[128][TSTRIDE];
    __shared__ __nv_bfloat16 BsL[128][TSTRIDE];

    const int t    = threadIdx.x;
    const int wid  = t >> 5;
    const int lane = t & 31;
    const int bm   = blockIdx.y * 128;
    const int bn   = blockIdx.x * 128;

    const int warp_m = wid & 1;
    const int warp_n = wid >> 1;
    const int r   = lane >> 2;
    const int c2  = (lane & 3) * 2;

    float acc[4][4][4];
#pragma unroll
    for (int f = 0; f < 4; f++)
#pragma unroll
        for (int g = 0; g < 4; g++)
#pragma unroll
            for (int u = 0; u < 4; u++) acc[f][g][u] = 0.0f;

    for (int k0 = 0; k0 < CD; k0 += 32) {
        __syncthreads();
#pragma unroll
        for (int i = 0; i < 2; i++) {
            const int idx = t + 256 * i;
            const int row = idx >> 2;
            const int ch  = idx & 3;
            const size_t ga = (size_t)(bm + row) * CD + k0 + ch * 8;
            const size_t gb = (size_t)(bn + row) * CD + k0 + ch * 8;
            *(uint4*)&AsH[row][ch * 8] = *(const uint4*)&Ah[ga];
            *(uint4*)&AsL[row][ch * 8] = *(const uint4*)&Al[ga];
            *(uint4*)&BsH[row][ch * 8] = *(const uint4*)&Bh[gb];
            *(uint4*)&BsL[row][ch * 8] = *(const uint4*)&Bl[gb];
        }
        __syncthreads();

#pragma unroll
        for (int s = 0; s < 2; s++) {
            const int kb = s * 16;
            uint32_t aH[4][4], aL[4][4], bH[4][2], bL[4][2];
#pragma unroll
            for (int f = 0; f < 4; f++) {
                const int m0 = warp_m * 64 + f * 16 + r;
                aH[f][0] = *(const uint32_t*)&AsH[m0    ][kb + c2];
                aH[f][1] = *(const uint32_t*)&AsH[m0 + 8][kb + c2];
                aH[f][2] = *(const uint32_t*)&AsH[m0    ][kb + 8 + c2];
                aH[f][3] = *(const uint32_t*)&AsH[m0 + 8][kb + 8 + c2];
                aL[f][0] = *(const uint32_t*)&AsL[m0    ][kb + c2];
                aL[f][1] = *(const uint32_t*)&AsL[m0 + 8][kb + c2];
                aL[f][2] = *(const uint32_t*)&AsL[m0    ][kb + 8 + c2];
                aL[f][3] = *(const uint32_t*)&AsL[m0 + 8][kb + 8 + c2];
            }
#pragma unroll
            for (int g = 0; g < 4; g++) {
                const int n0 = warp_n * 32 + g * 8 + r;
                bH[g][0] = *(const uint32_t*)&BsH[n0][kb + c2];
                bH[g][1] = *(const uint32_t*)&BsH[n0][kb + 8 + c2];
                bL[g][0] = *(const uint32_t*)&BsL[n0][kb + c2];
                bL[g][1] = *(const uint32_t*)&BsL[n0][kb + 8 + c2];
            }
#pragma unroll
            for (int f = 0; f < 4; f++)
#pragma unroll
                for (int g = 0; g < 4; g++) {
                    mma16816(acc[f][g], aH[f], bH[g]);
                    mma16816(acc[f][g], aH[f], bL[g]);
                    mma16816(acc[f][g], aL[f], bH[g]);
                }
        }
    }

#pragma unroll
    for (int f = 0; f < 4; f++) {
        const int gm0 = bm + warp_m * 64 + f * 16 + r;
#pragma unroll
        for (int g = 0; g < 4; g++) {
            const int gc = bn + warp_n * 32 + g * 8 + c2;
            if (MODE == 0) {
                const int s = gc / CD;
                const int h = (gc % CD) / HD;
                const int d = gc % HD;
                __nv_bfloat16* dsth = (s == 0) ? g_qh : (s == 1) ? g_kh : g_vh;
                __nv_bfloat16* dstl = (s == 0) ? g_ql : (s == 1) ? g_kl : g_vl;
#pragma unroll
                for (int hrow = 0; hrow < 2; hrow++) {
                    const int gm = gm0 + hrow * 8;
                    const int b  = gm >> 10;
                    const int n  = gm & 1023;
                    uint32_t hv, lv;
                    split2(acc[f][g][hrow * 2], acc[f][g][hrow * 2 + 1], hv, lv);
                    const size_t idx =
                        ((size_t)(b * NH + h) * SEQ + n) * HD + d;
                    *(uint32_t*)&dsth[idx] = hv;
                    *(uint32_t*)&dstl[idx] = lv;
                }
            } else {
                const float b0 = bias[gc], b1 = bias[gc + 1];
#pragma unroll
                for (int hrow = 0; hrow < 2; hrow++) {
                    const int gm = gm0 + hrow * 8;
                    float2 o = make_float2(acc[f][g][hrow * 2] + b0,
                                           acc[f][g][hrow * 2 + 1] + b1);
                    *(float2*)&Cout[(size_t)gm * CD + gc] = o;
                }
            }
        }
    }
}

// ---------------------------------------------------------------------------
// Quad2 attention on mma.sync (bf16 hi/lo split everywhere, fp32 accum).
// CTA: 128 Q-rows x one (b,h). 8 warps, each owns 16 rows (full kv width).
// KV tiles of 128. S-frag -> P A-frag register repack; V via ldmatrix.trans.
// ATSTRIDE = 72 (64 data + 8 pad): R11 crash was reusing TSTRIDE=40 for
// 64-wide tiles (8 KB overflow per tile, ran off the SMEM allocation).
// word pitch 36 ≡ 4 (mod 32) => frag rows r=0..7 cover banks 4r+{0..3}:
// conflict-free LDS + ldmatrix; row pitch 144 B is 16B-aligned.
// ---------------------------------------------------------------------------
#define ATSTRIDE  72
#define AT_TILE_E (128 * ATSTRIDE)            // elems per smem tile (9216)
#define AT_SMEM_B (6 * AT_TILE_E * 2)         // 110592 bytes

__global__ __launch_bounds__(256)
void attn_mma_kernel() {
    extern __shared__ __nv_bfloat16 sm[];
    __nv_bfloat16* sQh = sm;
    __nv_bfloat16* sQl = sm + AT_TILE_E;
    __nv_bfloat16* sKh = sm + 2 * AT_TILE_E;
    __nv_bfloat16* sKl = sm + 3 * AT_TILE_E;
    __nv_bfloat16* sVh = sm + 4 * AT_TILE_E;
    __nv_bfloat16* sVl = sm + 5 * AT_TILE_E;

    const int bh = blockIdx.y;
    const int r0 = blockIdx.x * 128;
    const size_t hb = (size_t)bh * SEQ * HD;

    const int t    = threadIdx.x;
    const int wid  = t >> 5;
    const int lane = t & 31;
    const int r    = lane >> 2;
    const int c2   = (lane & 3) * 2;

    // Load Q tile (128 x 64, hi+lo) once
#pragma unroll
    for (int i = 0; i < 4; i++) {
        const int idx = t + 256 * i;          // 0..1023
        const int row = idx >> 3;
        const int ch  = idx & 7;
        const size_t g = hb + (size_t)(r0 + row) * HD + ch * 8;
        *(uint4*)&sQh[row * ATSTRIDE + ch * 8] = *(const uint4*)&g_qh[g];
        *(uint4*)&sQl[row * ATSTRIDE + ch * 8] = *(const uint4*)&g_ql[g];
    }

    float O[8][4];
#pragma unroll
    for (int p = 0; p < 8; p++)
#pragma unroll
        for (int u = 0; u < 4; u++) O[p][u] = 0.0f;
    float den_r = 0.0f, den_r8 = 0.0f;

    const int m0r = wid * 16 + r;
    // ldmatrix lane address components (V tile)
    const int ld_row = (lane & 7) + 8 * ((lane >> 3) & 1);
    const int ld_col = 8 * (lane >> 4);
    const uint32_t vh_base = smem_u32(sVh);
    const uint32_t vl_base = smem_u32(sVl);

    for (int m0 = 0; m0 < SEQ; m0 += 128) {
        __syncthreads();   // protect previous iter's K/V reads
        // Load K and V tiles (128 x 64 hi+lo each)
#pragma unroll
        for (int i = 0; i < 4; i++) {
            const int idx = t + 256 * i;
            const int row = idx >> 3;
            const int ch  = idx & 7;
            const size_t g = hb + (size_t)(m0 + row) * HD + ch * 8;
            const int so = row * ATSTRIDE + ch * 8;
            *(uint4*)&sKh[so] = *(const uint4*)&g_kh[g];
            *(uint4*)&sKl[so] = *(const uint4*)&g_kl[g];
            *(uint4*)&sVh[so] = *(const uint4*)&g_vh[g];
            *(uint4*)&sVl[so] = *(const uint4*)&g_vl[g];
        }
        __syncthreads();

        // ---- Phase A: S[16 rows][128 kv] = Q K^T (hi/lo, fp32 accum) ----
        float S[16][4];
#pragma unroll
        for (int j = 0; j < 16; j++)
#pragma unroll
            for (int u = 0; u < 4; u++) S[j][u] = 0.0f;

#pragma unroll
        for (int ks = 0; ks < 4; ks++) {
            const int kb = ks * 16;
            uint32_t ah[4], al[4];
            ah[0] = *(const uint32_t*)&sQh[(m0r    ) * ATSTRIDE + kb + c2];
            ah[1] = *(const uint32_t*)&sQh[(m0r + 8) * ATSTRIDE + kb + c2];
            ah[2] = *(const uint32_t*)&sQh[(m0r    ) * ATSTRIDE + kb + 8 + c2];
            ah[3] = *(const uint32_t*)&sQh[(m0r + 8) * ATSTRIDE + kb + 8 + c2];
            al[0] = *(const uint32_t*)&sQl[(m0r    ) * ATSTRIDE + kb + c2];
            al[1] = *(const uint32_t*)&sQl[(m0r + 8) * ATSTRIDE + kb + c2];
            al[2] = *(const uint32_t*)&sQl[(m0r    ) * ATSTRIDE + kb + 8 + c2];
            al[3] = *(const uint32_t*)&sQl[(m0r + 8) * ATSTRIDE + kb + 8 + c2];
#pragma unroll
            for (int j = 0; j < 16; j++) {
                const int n0 = j * 8 + r;
                uint32_t bh2[2], bl2[2];
                bh2[0] = *(const uint32_t*)&sKh[n0 * ATSTRIDE + kb + c2];
                bh2[1] = *(const uint32_t*)&sKh[n0 * ATSTRIDE + kb + 8 + c2];
                bl2[0] = *(const uint32_t*)&sKl[n0 * ATSTRIDE + kb + c2];
                bl2[1] = *(const uint32_t*)&sKl[n0 * ATSTRIDE + kb + 8 + c2];
                mma16816(S[j], ah, bh2);
                mma16816(S[j], ah, bl2);
                mma16816(S[j], al, bh2);
            }
        }

        // ---- Phase B: quad2 transform, P hi/lo repack, P @ V ----
#pragma unroll
        for (int ks = 0; ks < 8; ks++) {
            const int j = 2 * ks;
            float tv[8];
#pragma unroll
            for (int u = 0; u < 4; u++) {
                float s0 = S[j][u]     * SCALE + QUADC;
                float s1 = S[j + 1][u] * SCALE + QUADC;
                tv[u]     = s0 * s0;
                tv[4 + u] = s1 * s1;
            }
            den_r  += tv[0] + tv[1] + tv[4] + tv[5];
            den_r8 += tv[2] + tv[3] + tv[6] + tv[7];

            uint32_t a_h[4], a_l[4];
            split2(tv[0], tv[1], a_h[0], a_l[0]);   // (r,   k0..1)
            split2(tv[2], tv[3], a_h[1], a_l[1]);   // (r+8, k0..1)
            split2(tv[4], tv[5], a_h[2], a_l[2]);   // (r,   k0+8..9)
            split2(tv[6], tv[7], a_h[3], a_l[3]);   // (r+8, k0+8..9)

            const int kb = ks * 16;
            const uint32_t lofs =
                (uint32_t)(((kb + ld_row) * ATSTRIDE + ld_col) * 2);
#pragma unroll
            for (int p = 0; p < 4; p++) {
                uint32_t vh4[4], vl4[4];
                ldmx4t(vh4, vh_base + lofs + p * 32);   // n0 = 16p -> +32B
                ldmx4t(vl4, vl_base + lofs + p * 32);
                mma16816(O[2 * p],     a_h, &vh4[0]);
                mma16816(O[2 * p],     a_h, &vl4[0]);
                mma16816(O[2 * p],     a_l, &vh4[0]);
                mma16816(O[2 * p + 1], a_h, &vh4[2]);
                mma16816(O[2 * p + 1], a_h, &vl4[2]);
                mma16816(O[2 * p + 1], a_l, &vh4[2]);
            }
        }
    }

    // Quad reduction: lanes 4r..4r+3 hold disjoint column partials
    den_r  += __shfl_xor_sync(0xffffffffu, den_r, 1);
    den_r  += __shfl_xor_sync(0xffffffffu, den_r, 2);
    den_r8 += __shfl_xor_sync(0xffffffffu, den_r8, 1);
    den_r8 += __shfl_xor_sync(0xffffffffu, den_r8, 2);
    const float inv0 = 1.0f / den_r;
    const float inv1 = 1.0f / den_r8;

    const int b = bh / NH;
    const int h = bh % NH;
    const int row0 = r0 + wid * 16 + r;
    const size_t base0 = ((size_t)(b * SEQ + row0))     * CD + h * HD;
    const size_t base1 = ((size_t)(b * SEQ + row0 + 8)) * CD + h * HD;
#pragma unroll
    for (int p = 0; p < 8; p++) {
        const int d0 = p * 8 + c2;
        uint32_t h0, l0, h1, l1;
        split2(O[p][0] * inv0, O[p][1] * inv0, h0, l0);
        split2(O[p][2] * inv1, O[p][3] * inv1, h1, l1);
        *(uint32_t*)&g_ath[base0 + d0] = h0;
        *(uint32_t*)&g_atl[base0 + d0] = l0;
        *(uint32_t*)&g_ath[base1 + d0] = h1;
        *(uint32_t*)&g_atl[base1 + d0] = l1;
    }
}

// ---------------------------------------------------------------------------
extern "C" void kernel_launch(void* const* d_in, const int* in_sizes, int n_in,
                              void* d_out, int out_size) {
    const float* x = nullptr;
    const float* qkv_w = nullptr;
    const float* proj_w = nullptr;
    const float* proj_b = nullptr;
    for (int i = 0; i < n_in; i++) {
        switch (in_sizes[i]) {
            case MTOT * CD: x      = (const float*)d_in[i]; break;
            case QKVN * CD: qkv_w  = (const float*)d_in[i]; break;
            case CD * CD:   proj_w = (const float*)d_in[i]; break;
            case CD:        proj_b = (const float*)d_in[i]; break;
            default: break;
        }
    }
    float* out = (float*)d_out;

    // Device addresses of __device__ symbols (host shadow addr = R4 trap)
    __nv_bfloat16 *xh, *xl, *wh, *wl, *ph, *pl, *ath, *atl;
    cudaGetSymbolAddress((void**)&xh,  g_xh);
    cudaGetSymbolAddress((void**)&xl,  g_xl);
    cudaGetSymbolAddress((void**)&wh,  g_wh);
    cudaGetSymbolAddress((void**)&wl,  g_wl);
    cudaGetSymbolAddress((void**)&ph,  g_ph);
    cudaGetSymbolAddress((void**)&pl,  g_pl);
    cudaGetSymbolAddress((void**)&ath, g_ath);
    cudaGetSymbolAddress((void**)&atl, g_atl);

    cudaFuncSetAttribute(attn_mma_kernel,
                         cudaFuncAttributeMaxDynamicSharedMemorySize, AT_SMEM_B);

    // 0) split fp32 inputs into bf16 hi/lo
    split_kernel<<<(MTOT * CD) / (256 * 4), 256>>>(x, xh, xl, MTOT * CD);
    split_kernel<<<(QKVN * CD) / (256 * 4), 256>>>(qkv_w, wh, wl, QKVN * CD);
    split_kernel<<<(CD * CD)   / (256 * 4), 256>>>(proj_w, ph, pl, CD * CD);

    // 1) qkv projection (tensor cores) -> bf16 hi/lo q/k/v
    tc_gemm_kernel<0><<<dim3(QKVN / 128, MTOT / 128), 256>>>(
        xh, xl, wh, wl, nullptr, nullptr);

    // 2) quad2 attention (tensor cores) -> g_ath/g_atl
    attn_mma_kernel<<<dim3(SEQ / 128, BB * NH), 256, AT_SMEM_B>>>();

    // 3) output projection + bias (tensor cores)
    tc_gemm_kernel<1><<<dim3(CD / 128, MTOT / 128), 256>>>(
        ath, atl, ph, pl, out, proj_b);
}

// round 14
// speedup vs baseline: 2.9212x; 1.1576x over previous
#include <cuda_runtime.h>
#include <cuda_bf16.h>
#include <cstdint>

// ---------------------------------------------------------------------------
// Problem constants
// ---------------------------------------------------------------------------
#define BB    8
#define SEQ   1024
#define CD    768
#define NH    12
#define HD    64
#define MTOT  (BB * SEQ)        // 8192
#define QKVN  (3 * CD)          // 2304
#define SCALE 0.125f
#define QUADC 5.0f

// ---------------------------------------------------------------------------
// Scratch (device globals — no allocation allowed)
// ---------------------------------------------------------------------------
__device__ __nv_bfloat16 g_qh[BB * NH * SEQ * HD];
__device__ __nv_bfloat16 g_ql[BB * NH * SEQ * HD];
__device__ __nv_bfloat16 g_kh[BB * NH * SEQ * HD];
__device__ __nv_bfloat16 g_kl[BB * NH * SEQ * HD];
__device__ __nv_bfloat16 g_vh[BB * NH * SEQ * HD];
__device__ __nv_bfloat16 g_vl[BB * NH * SEQ * HD];
__device__ __nv_bfloat16 g_xh[MTOT * CD];
__device__ __nv_bfloat16 g_xl[MTOT * CD];
__device__ __nv_bfloat16 g_wh[QKVN * CD];
__device__ __nv_bfloat16 g_wl[QKVN * CD];
__device__ __nv_bfloat16 g_ph[CD * CD];
__device__ __nv_bfloat16 g_pl[CD * CD];
__device__ __nv_bfloat16 g_ath[MTOT * CD];   // attention out hi ([B,N,C])
__device__ __nv_bfloat16 g_atl[MTOT * CD];   // attention out lo

// ---------------------------------------------------------------------------
// mma.sync m16n8k16 bf16 (sm_80+; tcgen05 PTX rejected at compute_103 — R7)
// Frag maps (verified): A a0=(r,k0) a1=(r+8,k0) a2=(r,k0+8) a3=(r+8,k0+8);
// B b0=(n=r,k0) b1=(n=r,k0+8); C c0=(r,2c) c1=(r,2c+1) c2/c3 at r+8.
// ---------------------------------------------------------------------------
__device__ __forceinline__ void mma16816(float* d, const uint32_t* a,
                                         const uint32_t* b) {
    asm volatile(
        "mma.sync.aligned.m16n8k16.row.col.f32.bf16.bf16.f32 "
        "{%0,%1,%2,%3}, {%4,%5,%6,%7}, {%8,%9}, {%0,%1,%2,%3};"
        : "+f"(d[0]), "+f"(d[1]), "+f"(d[2]), "+f"(d[3])
        : "r"(a[0]), "r"(a[1]), "r"(a[2]), "r"(a[3]),
          "r"(b[0]), "r"(b[1]));
}

__device__ __forceinline__ void ldmx4t(uint32_t* d, uint32_t addr) {
    asm volatile(
        "ldmatrix.sync.aligned.m8n8.x4.trans.shared.b16 {%0,%1,%2,%3}, [%4];"
        : "=r"(d[0]), "=r"(d[1]), "=r"(d[2]), "=r"(d[3]) : "r"(addr));
}

__device__ __forceinline__ uint32_t smem_u32(const void* p) {
    uint32_t a;
    asm("{ .reg .u64 t; cvta.to.shared.u64 t, %1; cvt.u32.u64 %0, t; }"
        : "=r"(a) : "l"(p));
    return a;
}

// cp.async 16B global->shared (LDGSTS)
__device__ __forceinline__ void cp16(uint32_t smem, const void* gptr) {
    asm volatile("cp.async.cg.shared.global [%0], [%1], 16;"
                 :: "r"(smem), "l"(gptr) : "memory");
}
#define CP_COMMIT() asm volatile("cp.async.commit_group;" ::: "memory")
template <int N>
__device__ __forceinline__ void cp_wait() {
    asm volatile("cp.async.wait_group %0;" :: "n"(N) : "memory");
}

// split two fp32 into packed bf16x2 hi + bf16x2 lo
__device__ __forceinline__ void split2(float x, float y,
                                       uint32_t& hi, uint32_t& lo) {
    __nv_bfloat16 hx = __float2bfloat16(x);
    __nv_bfloat16 hy = __float2bfloat16(y);
    __nv_bfloat16 lx = __float2bfloat16(x - __bfloat162float(hx));
    __nv_bfloat16 ly = __float2bfloat16(y - __bfloat162float(hy));
    hi = ((uint32_t)__bfloat16_as_ushort(hy) << 16) |
         (uint32_t)__bfloat16_as_ushort(hx);
    lo = ((uint32_t)__bfloat16_as_ushort(ly) << 16) |
         (uint32_t)__bfloat16_as_ushort(lx);
}

// ---------------------------------------------------------------------------
// fp32 -> bf16 hi/lo split (elementwise)
// ---------------------------------------------------------------------------
__global__ void split_kernel(const float* __restrict__ src,
                             __nv_bfloat16* __restrict__ dh,
                             __nv_bfloat16* __restrict__ dl, int n) {
    int i = (blockIdx.x * 256 + threadIdx.x) * 4;
    if (i >= n) return;
    float4 v = *(const float4*)&src[i];
    uint32_t h01, l01, h23, l23;
    split2(v.x, v.y, h01, l01);
    split2(v.z, v.w, h23, l23);
    *(uint32_t*)&dh[i]     = h01;  *(uint32_t*)&dh[i + 2] = h23;
    *(uint32_t*)&dl[i]     = l01;  *(uint32_t*)&dl[i + 2] = l23;
}

// ---------------------------------------------------------------------------
// Tensor-core GEMM:  C[M,N] = A[M,768] @ B[N,768]^T  (bf16 hi/lo, fp32 accum)
// CTA 128x128, BK=32, 8 warps, warp tile 64x32.
// cp.async double-buffered K loop (R13): tile c+1 streams while c computes.
// MODE 0: scatter bf16 hi/lo into g_q*/g_k*/g_v*   MODE 1: fp32 + bias
// ---------------------------------------------------------------------------
#define TSTRIDE 40
#define GT_E    (128 * TSTRIDE)              // elems per tile (5120)
#define GBUF_E  (4 * GT_E)                   // Ah, Al, Bh, Bl
#define GS_B    (2 * GBUF_E * 2)             // 81920 bytes
#define NCHUNK  (CD / 32)                    // 24

template <int MODE>
__global__ __launch_bounds__(256)
void tc_gemm_kernel(const __nv_bfloat16* __restrict__ Ah,
                    const __nv_bfloat16* __restrict__ Al,
                    const __nv_bfloat16* __restrict__ Bh,
                    const __nv_bfloat16* __restrict__ Bl,
                    float* __restrict__ Cout,
                    const float* __restrict__ bias) {
    extern __shared__ __nv_bfloat16 gsm[];
    const uint32_t sbase = smem_u32(gsm);

    const int t    = threadIdx.x;
    const int wid  = t >> 5;
    const int lane = t & 31;
    const int bm   = blockIdx.y * 128;
    const int bn   = blockIdx.x * 128;

    const int warp_m = wid & 1;
    const int warp_n = wid >> 1;
    const int r   = lane >> 2;
    const int c2  = (lane & 3) * 2;

    // Per-thread load coords (2 chunks of 16B per tile)
    const int lrow0 = t >> 2;                 // idx = t       -> row
    const int lch0  = t & 3;
    const int lrow1 = (t + 256) >> 2;
    const int lch1  = (t + 256) & 3;

    const __nv_bfloat16* srcs[4] = {Ah, Al, Bh, Bl};

    auto load_tiles = [&](int c, int buf) {
        const int k0 = c * 32;
        const uint32_t bofs = (uint32_t)(buf * GBUF_E) * 2;
#pragma unroll
        for (int tt = 0; tt < 4; tt++) {
            const int base_row = (tt < 2) ? bm : bn;
            const uint32_t tofs = bofs + (uint32_t)(tt * GT_E) * 2;
            cp16(sbase + tofs + (uint32_t)(lrow0 * TSTRIDE + lch0 * 8) * 2,
                 &srcs[tt][(size_t)(base_row + lrow0) * CD + k0 + lch0 * 8]);
            cp16(sbase + tofs + (uint32_t)(lrow1 * TSTRIDE + lch1 * 8) * 2,
                 &srcs[tt][(size_t)(base_row + lrow1) * CD + k0 + lch1 * 8]);
        }
    };

    float acc[4][4][4];
#pragma unroll
    for (int f = 0; f < 4; f++)
#pragma unroll
        for (int g = 0; g < 4; g++)
#pragma unroll
            for (int u = 0; u < 4; u++) acc[f][g][u] = 0.0f;

    load_tiles(0, 0);
    CP_COMMIT();

    for (int c = 0; c < NCHUNK; c++) {
        const int cb = c & 1;
        if (c + 1 < NCHUNK) {
            load_tiles(c + 1, cb ^ 1);
            CP_COMMIT();
            cp_wait<1>();            // group c done; c+1 may be in flight
        } else {
            cp_wait<0>();
        }
        __syncthreads();

        const __nv_bfloat16* AsH = gsm + cb * GBUF_E;
        const __nv_bfloat16* AsL = AsH + GT_E;
        const __nv_bfloat16* BsH = AsH + 2 * GT_E;
        const __nv_bfloat16* BsL = AsH + 3 * GT_E;

#pragma unroll
        for (int s = 0; s < 2; s++) {
            const int kb = s * 16;
            uint32_t aH[4][4], aL[4][4], bH[4][2], bL[4][2];
#pragma unroll
            for (int f = 0; f < 4; f++) {
                const int m0 = warp_m * 64 + f * 16 + r;
                aH[f][0] = *(const uint32_t*)&AsH[m0 * TSTRIDE + kb + c2];
                aH[f][1] = *(const uint32_t*)&AsH[(m0 + 8) * TSTRIDE + kb + c2];
                aH[f][2] = *(const uint32_t*)&AsH[m0 * TSTRIDE + kb + 8 + c2];
                aH[f][3] = *(const uint32_t*)&AsH[(m0 + 8) * TSTRIDE + kb + 8 + c2];
                aL[f][0] = *(const uint32_t*)&AsL[m0 * TSTRIDE + kb + c2];
                aL[f][1] = *(const uint32_t*)&AsL[(m0 + 8) * TSTRIDE + kb + c2];
                aL[f][2] = *(const uint32_t*)&AsL[m0 * TSTRIDE + kb + 8 + c2];
                aL[f][3] = *(const uint32_t*)&AsL[(m0 + 8) * TSTRIDE + kb + 8 + c2];
            }
#pragma unroll
            for (int g = 0; g < 4; g++) {
                const int n0 = warp_n * 32 + g * 8 + r;
                bH[g][0] = *(const uint32_t*)&BsH[n0 * TSTRIDE + kb + c2];
                bH[g][1] = *(const uint32_t*)&BsH[n0 * TSTRIDE + kb + 8 + c2];
                bL[g][0] = *(const uint32_t*)&BsL[n0 * TSTRIDE + kb + c2];
                bL[g][1] = *(const uint32_t*)&BsL[n0 * TSTRIDE + kb + 8 + c2];
            }
#pragma unroll
            for (int f = 0; f < 4; f++)
#pragma unroll
                for (int g = 0; g < 4; g++) {
                    mma16816(acc[f][g], aH[f], bH[g]);
                    mma16816(acc[f][g], aH[f], bL[g]);
                    mma16816(acc[f][g], aL[f], bH[g]);
                }
        }
        __syncthreads();             // reads done before buffer rewrite
    }

#pragma unroll
    for (int f = 0; f < 4; f++) {
        const int gm0 = bm + warp_m * 64 + f * 16 + r;
#pragma unroll
        for (int g = 0; g < 4; g++) {
            const int gc = bn + warp_n * 32 + g * 8 + c2;
            if (MODE == 0) {
                const int s = gc / CD;
                const int h = (gc % CD) / HD;
                const int d = gc % HD;
                __nv_bfloat16* dsth = (s == 0) ? g_qh : (s == 1) ? g_kh : g_vh;
                __nv_bfloat16* dstl = (s == 0) ? g_ql : (s == 1) ? g_kl : g_vl;
#pragma unroll
                for (int hrow = 0; hrow < 2; hrow++) {
                    const int gm = gm0 + hrow * 8;
                    const int b  = gm >> 10;
                    const int n  = gm & 1023;
                    uint32_t hv, lv;
                    split2(acc[f][g][hrow * 2], acc[f][g][hrow * 2 + 1], hv, lv);
                    const size_t idx =
                        ((size_t)(b * NH + h) * SEQ + n) * HD + d;
                    *(uint32_t*)&dsth[idx] = hv;
                    *(uint32_t*)&dstl[idx] = lv;
                }
            } else {
                const float b0 = bias[gc], b1 = bias[gc + 1];
#pragma unroll
                for (int hrow = 0; hrow < 2; hrow++) {
                    const int gm = gm0 + hrow * 8;
                    float2 o = make_float2(acc[f][g][hrow * 2] + b0,
                                           acc[f][g][hrow * 2 + 1] + b1);
                    *(float2*)&Cout[(size_t)gm * CD + gc] = o;
                }
            }
        }
    }
}

// ---------------------------------------------------------------------------
// Quad2 attention on mma.sync (bf16 hi/lo, fp32 accum), cp.async-pipelined.
// CTA: 128 Q-rows x one (b,h). 8 warps x 16 rows. KV tiles of 128,
// double-buffered (Kh,Kl,Vh,Vl per buffer). ATSTRIDE=72 (R11 lesson).
// ---------------------------------------------------------------------------
#define ATSTRIDE  72
#define AT_TILE_E (128 * ATSTRIDE)            // 9216
#define AT_KVBUF  (4 * AT_TILE_E)             // tiles: Kh,Kl,Vh,Vl
#define AT_SMEM_B ((2 * AT_TILE_E + 2 * AT_KVBUF) * 2)   // 184320 bytes

__global__ __launch_bounds__(256)
void attn_mma_kernel() {
    extern __shared__ __nv_bfloat16 sm[];
    __nv_bfloat16* sQh = sm;
    __nv_bfloat16* sQl = sm + AT_TILE_E;
    __nv_bfloat16* kv0 = sm + 2 * AT_TILE_E;   // [2][4][AT_TILE_E]
    const uint32_t kv_u32 = smem_u32(kv0);

    const int bh = blockIdx.y;
    const int r0 = blockIdx.x * 128;
    const size_t hb = (size_t)bh * SEQ * HD;

    const int t    = threadIdx.x;
    const int wid  = t >> 5;
    const int lane = t & 31;
    const int r    = lane >> 2;
    const int c2   = (lane & 3) * 2;

    // Load Q tile (128 x 64, hi+lo) once — plain stores
#pragma unroll
    for (int i = 0; i < 4; i++) {
        const int idx = t + 256 * i;
        const int row = idx >> 3;
        const int ch  = idx & 7;
        const size_t g = hb + (size_t)(r0 + row) * HD + ch * 8;
        *(uint4*)&sQh[row * ATSTRIDE + ch * 8] = *(const uint4*)&g_qh[g];
        *(uint4*)&sQl[row * ATSTRIDE + ch * 8] = *(const uint4*)&g_ql[g];
    }

    // Per-thread KV load coords: 4 chunks of 16B per tile
    const __nv_bfloat16* kvsrc[4];
    kvsrc[0] = g_kh; kvsrc[1] = g_kl; kvsrc[2] = g_vh; kvsrc[3] = g_vl;

    auto load_kv = [&](int m0, int buf) {
        const uint32_t bofs = (uint32_t)(buf * AT_KVBUF) * 2;
#pragma unroll
        for (int i = 0; i < 4; i++) {
            const int idx = t + 256 * i;        // 0..1023
            const int row = idx >> 3;
            const int ch  = idx & 7;
            const size_t g = hb + (size_t)(m0 + row) * HD + ch * 8;
            const uint32_t so = (uint32_t)(row * ATSTRIDE + ch * 8) * 2;
#pragma unroll
            for (int tt = 0; tt < 4; tt++)
                cp16(kv_u32 + bofs + (uint32_t)(tt * AT_TILE_E) * 2 + so,
                     &kvsrc[tt][g]);
        }
    };

    float O[8][4];
#pragma unroll
    for (int p = 0; p < 8; p++)
#pragma unroll
        for (int u = 0; u < 4; u++) O[p][u] = 0.0f;
    float den_r = 0.0f, den_r8 = 0.0f;

    const int m0r = wid * 16 + r;
    const int ld_row = (lane & 7) + 8 * ((lane >> 3) & 1);
    const int ld_col = 8 * (lane >> 4);

    load_kv(0, 0);
    CP_COMMIT();

    for (int it = 0; it < SEQ / 128; it++) {
        const int kb_ = it & 1;
        if (it + 1 < SEQ / 128) {
            load_kv((it + 1) * 128, kb_ ^ 1);
            CP_COMMIT();
            cp_wait<1>();
        } else {
            cp_wait<0>();
        }
        __syncthreads();

        const __nv_bfloat16* sKh = kv0 + kb_ * AT_KVBUF;
        const __nv_bfloat16* sKl = sKh + AT_TILE_E;
        const uint32_t vh_base = kv_u32 +
            (uint32_t)(kb_ * AT_KVBUF + 2 * AT_TILE_E) * 2;
        const uint32_t vl_base = vh_base + (uint32_t)AT_TILE_E * 2;

        // ---- Phase A: S[16 rows][128 kv] = Q K^T ----
        float S[16][4];
#pragma unroll
        for (int j = 0; j < 16; j++)
#pragma unroll
            for (int u = 0; u < 4; u++) S[j][u] = 0.0f;

#pragma unroll
        for (int ks = 0; ks < 4; ks++) {
            const int kb = ks * 16;
            uint32_t ah[4], al[4];
            ah[0] = *(const uint32_t*)&sQh[(m0r    ) * ATSTRIDE + kb + c2];
            ah[1] = *(const uint32_t*)&sQh[(m0r + 8) * ATSTRIDE + kb + c2];
            ah[2] = *(const uint32_t*)&sQh[(m0r    ) * ATSTRIDE + kb + 8 + c2];
            ah[3] = *(const uint32_t*)&sQh[(m0r + 8) * ATSTRIDE + kb + 8 + c2];
            al[0] = *(const uint32_t*)&sQl[(m0r    ) * ATSTRIDE + kb + c2];
            al[1] = *(const uint32_t*)&sQl[(m0r + 8) * ATSTRIDE + kb + c2];
            al[2] = *(const uint32_t*)&sQl[(m0r    ) * ATSTRIDE + kb + 8 + c2];
            al[3] = *(const uint32_t*)&sQl[(m0r + 8) * ATSTRIDE + kb + 8 + c2];
#pragma unroll
            for (int j = 0; j < 16; j++) {
                const int n0 = j * 8 + r;
                uint32_t bh2[2], bl2[2];
                bh2[0] = *(const uint32_t*)&sKh[n0 * ATSTRIDE + kb + c2];
                bh2[1] = *(const uint32_t*)&sKh[n0 * ATSTRIDE + kb + 8 + c2];
                bl2[0] = *(const uint32_t*)&sKl[n0 * ATSTRIDE + kb + c2];
                bl2[1] = *(const uint32_t*)&sKl[n0 * ATSTRIDE + kb + 8 + c2];
                mma16816(S[j], ah, bh2);
                mma16816(S[j], ah, bl2);
                mma16816(S[j], al, bh2);
            }
        }

        // ---- Phase B: quad2 transform, P hi/lo repack, P @ V ----
#pragma unroll
        for (int ks = 0; ks < 8; ks++) {
            const int j = 2 * ks;
            float tv[8];
#pragma unroll
            for (int u = 0; u < 4; u++) {
                float s0 = S[j][u]     * SCALE + QUADC;
                float s1 = S[j + 1][u] * SCALE + QUADC;
                tv[u]     = s0 * s0;
                tv[4 + u] = s1 * s1;
            }
            den_r  += tv[0] + tv[1] + tv[4] + tv[5];
            den_r8 += tv[2] + tv[3] + tv[6] + tv[7];

            uint32_t a_h[4], a_l[4];
            split2(tv[0], tv[1], a_h[0], a_l[0]);
            split2(tv[2], tv[3], a_h[1], a_l[1]);
            split2(tv[4], tv[5], a_h[2], a_l[2]);
            split2(tv[6], tv[7], a_h[3], a_l[3]);

            const int kbv = ks * 16;
            const uint32_t lofs =
                (uint32_t)(((kbv + ld_row) * ATSTRIDE + ld_col) * 2);
#pragma unroll
            for (int p = 0; p < 4; p++) {
                uint32_t vh4[4], vl4[4];
                ldmx4t(vh4, vh_base + lofs + p * 32);
                ldmx4t(vl4, vl_base + lofs + p * 32);
                mma16816(O[2 * p],     a_h, &vh4[0]);
                mma16816(O[2 * p],     a_h, &vl4[0]);
                mma16816(O[2 * p],     a_l, &vh4[0]);
                mma16816(O[2 * p + 1], a_h, &vh4[2]);
                mma16816(O[2 * p + 1], a_h, &vl4[2]);
                mma16816(O[2 * p + 1], a_l, &vh4[2]);
            }
        }
        __syncthreads();             // reads done before buffer rewrite
    }

    // Quad reduction: lanes 4r..4r+3 hold disjoint column partials
    den_r  += __shfl_xor_sync(0xffffffffu, den_r, 1);
    den_r  += __shfl_xor_sync(0xffffffffu, den_r, 2);
    den_r8 += __shfl_xor_sync(0xffffffffu, den_r8, 1);
    den_r8 += __shfl_xor_sync(0xffffffffu, den_r8, 2);
    const float inv0 = 1.0f / den_r;
    const float inv1 = 1.0f / den_r8;

    const int b = bh / NH;
    const int h = bh % NH;
    const int row0 = r0 + wid * 16 + r;
    const size_t base0 = ((size_t)(b * SEQ + row0))     * CD + h * HD;
    const size_t base1 = ((size_t)(b * SEQ + row0 + 8)) * CD + h * HD;
#pragma unroll
    for (int p = 0; p < 8; p++) {
        const int d0 = p * 8 + c2;
        uint32_t h0, l0, h1, l1;
        split2(O[p][0] * inv0, O[p][1] * inv0, h0, l0);
        split2(O[p][2] * inv1, O[p][3] * inv1, h1, l1);
        *(uint32_t*)&g_ath[base0 + d0] = h0;
        *(uint32_t*)&g_atl[base0 + d0] = l0;
        *(uint32_t*)&g_ath[base1 + d0] = h1;
        *(uint32_t*)&g_atl[base1 + d0] = l1;
    }
}

// ---------------------------------------------------------------------------
extern "C" void kernel_launch(void* const* d_in, const int* in_sizes, int n_in,
                              void* d_out, int out_size) {
    const float* x = nullptr;
    const float* qkv_w = nullptr;
    const float* proj_w = nullptr;
    const float* proj_b = nullptr;
    for (int i = 0; i < n_in; i++) {
        switch (in_sizes[i]) {
            case MTOT * CD: x      = (const float*)d_in[i]; break;
            case QKVN * CD: qkv_w  = (const float*)d_in[i]; break;
            case CD * CD:   proj_w = (const float*)d_in[i]; break;
            case CD:        proj_b = (const float*)d_in[i]; break;
            default: break;
        }
    }
    float* out = (float*)d_out;

    // Device addresses of __device__ symbols (host shadow addr = R4 trap)
    __nv_bfloat16 *xh, *xl, *wh, *wl, *ph, *pl, *ath, *atl;
    cudaGetSymbolAddress((void**)&xh,  g_xh);
    cudaGetSymbolAddress((void**)&xl,  g_xl);
    cudaGetSymbolAddress((void**)&wh,  g_wh);
    cudaGetSymbolAddress((void**)&wl,  g_wl);
    cudaGetSymbolAddress((void**)&ph,  g_ph);
    cudaGetSymbolAddress((void**)&pl,  g_pl);
    cudaGetSymbolAddress((void**)&ath, g_ath);
    cudaGetSymbolAddress((void**)&atl, g_atl);

    cudaFuncSetAttribute(tc_gemm_kernel<0>,
                         cudaFuncAttributeMaxDynamicSharedMemorySize, GS_B);
    cudaFuncSetAttribute(tc_gemm_kernel<1>,
                         cudaFuncAttributeMaxDynamicSharedMemorySize, GS_B);
    cudaFuncSetAttribute(attn_mma_kernel,
                         cudaFuncAttributeMaxDynamicSharedMemorySize, AT_SMEM_B);

    // 0) split fp32 inputs into bf16 hi/lo
    split_kernel<<<(MTOT * CD) / (256 * 4), 256>>>(x, xh, xl, MTOT * CD);
    split_kernel<<<(QKVN * CD) / (256 * 4), 256>>>(qkv_w, wh, wl, QKVN * CD);
    split_kernel<<<(CD * CD)   / (256 * 4), 256>>>(proj_w, ph, pl, CD * CD);

    // 1) qkv projection (tensor cores) -> bf16 hi/lo q/k/v
    tc_gemm_kernel<0><<<dim3(QKVN / 128, MTOT / 128), 256, GS_B>>>(
        xh, xl, wh, wl, nullptr, nullptr);

    // 2) quad2 attention (tensor cores) -> g_ath/g_atl
    attn_mma_kernel<<<dim3(SEQ / 128, BB * NH), 256, AT_SMEM_B>>>();

    // 3) output projection + bias (tensor cores)
    tc_gemm_kernel<1><<<dim3(CD / 128, MTOT / 128), 256, GS_B>>>(
        ath, atl, ph, pl, out, proj_b);
}

// round 15
// speedup vs baseline: 3.1046x; 1.0628x over previous
#include <cuda_runtime.h>
#include <cuda_bf16.h>
#include <cstdint>

// ---------------------------------------------------------------------------
// Problem constants
// ---------------------------------------------------------------------------
#define BB    8
#define SEQ   1024
#define CD    768
#define NH    12
#define HD    64
#define MTOT  (BB * SEQ)        // 8192
#define QKVN  (3 * CD)          // 2304
#define SCALE 0.125f
#define QUADC 5.0f

// ---------------------------------------------------------------------------
// Scratch (device globals — no allocation allowed)
// ---------------------------------------------------------------------------
__device__ __nv_bfloat16 g_qh[BB * NH * SEQ * HD];
__device__ __nv_bfloat16 g_ql[BB * NH * SEQ * HD];
__device__ __nv_bfloat16 g_kh[BB * NH * SEQ * HD];
__device__ __nv_bfloat16 g_kl[BB * NH * SEQ * HD];
__device__ __nv_bfloat16 g_vh[BB * NH * SEQ * HD];
__device__ __nv_bfloat16 g_vl[BB * NH * SEQ * HD];
__device__ __nv_bfloat16 g_xh[MTOT * CD];
__device__ __nv_bfloat16 g_xl[MTOT * CD];
__device__ __nv_bfloat16 g_wh[QKVN * CD];
__device__ __nv_bfloat16 g_wl[QKVN * CD];
__device__ __nv_bfloat16 g_ph[CD * CD];
__device__ __nv_bfloat16 g_pl[CD * CD];
__device__ __nv_bfloat16 g_ath[MTOT * CD];
__device__ __nv_bfloat16 g_atl[MTOT * CD];

// ---------------------------------------------------------------------------
// mma.sync m16n8k16 bf16 helpers (tcgen05 PTX rejected at compute_103 — R7)
// ---------------------------------------------------------------------------
__device__ __forceinline__ void mma16816(float* d, const uint32_t* a,
                                         const uint32_t* b) {
    asm volatile(
        "mma.sync.aligned.m16n8k16.row.col.f32.bf16.bf16.f32 "
        "{%0,%1,%2,%3}, {%4,%5,%6,%7}, {%8,%9}, {%0,%1,%2,%3};"
        : "+f"(d[0]), "+f"(d[1]), "+f"(d[2]), "+f"(d[3])
        : "r"(a[0]), "r"(a[1]), "r"(a[2]), "r"(a[3]),
          "r"(b[0]), "r"(b[1]));
}

__device__ __forceinline__ void ldmx4t(uint32_t* d, uint32_t addr) {
    asm volatile(
        "ldmatrix.sync.aligned.m8n8.x4.trans.shared.b16 {%0,%1,%2,%3}, [%4];"
        : "=r"(d[0]), "=r"(d[1]), "=r"(d[2]), "=r"(d[3]) : "r"(addr));
}

__device__ __forceinline__ uint32_t smem_u32(const void* p) {
    uint32_t a;
    asm("{ .reg .u64 t; cvta.to.shared.u64 t, %1; cvt.u32.u64 %0, t; }"
        : "=r"(a) : "l"(p));
    return a;
}

__device__ __forceinline__ void cp16(uint32_t smem, const void* gptr) {
    asm volatile("cp.async.cg.shared.global [%0], [%1], 16;"
                 :: "r"(smem), "l"(gptr) : "memory");
}
#define CP_COMMIT() asm volatile("cp.async.commit_group;" ::: "memory")
template <int N>
__device__ __forceinline__ void cp_wait() {
    asm volatile("cp.async.wait_group %0;" :: "n"(N) : "memory");
}

__device__ __forceinline__ void split2(float x, float y,
                                       uint32_t& hi, uint32_t& lo) {
    __nv_bfloat16 hx = __float2bfloat16(x);
    __nv_bfloat16 hy = __float2bfloat16(y);
    __nv_bfloat16 lx = __float2bfloat16(x - __bfloat162float(hx));
    __nv_bfloat16 ly = __float2bfloat16(y - __bfloat162float(hy));
    hi = ((uint32_t)__bfloat16_as_ushort(hy) << 16) |
         (uint32_t)__bfloat16_as_ushort(hx);
    lo = ((uint32_t)__bfloat16_as_ushort(ly) << 16) |
         (uint32_t)__bfloat16_as_ushort(lx);
}

// ---------------------------------------------------------------------------
// fp32 -> bf16 hi/lo split
// ---------------------------------------------------------------------------
__global__ void split_kernel(const float* __restrict__ src,
                             __nv_bfloat16* __restrict__ dh,
                             __nv_bfloat16* __restrict__ dl, int n) {
    int i = (blockIdx.x * 256 + threadIdx.x) * 4;
    if (i >= n) return;
    float4 v = *(const float4*)&src[i];
    uint32_t h01, l01, h23, l23;
    split2(v.x, v.y, h01, l01);
    split2(v.z, v.w, h23, l23);
    *(uint32_t*)&dh[i]     = h01;  *(uint32_t*)&dh[i + 2] = h23;
    *(uint32_t*)&dl[i]     = l01;  *(uint32_t*)&dl[i + 2] = l23;
}

// ---------------------------------------------------------------------------
// Tensor-core GEMM:  C[M,N] = A[M,768] @ B[N,768]^T  (bf16 hi/lo, fp32 accum)
// R15: CTA 128x256, warp tile 64x64 (8 warps, 2x4) -> 48 FLOP/smem-byte
// (was 32 at 64x32; smem crossbar was the tensor-pipe cap at 47%).
// cp.async double-buffered. MODE 0: scatter hi/lo  MODE 1: fp32 + bias
// ---------------------------------------------------------------------------
#define TSTRIDE 40
#define GT_A    (128 * TSTRIDE)              // 5120
#define GT_B    (256 * TSTRIDE)              // 10240
#define GBUF_E  (2 * GT_A + 2 * GT_B)        // 30720
#define GS_B    (2 * GBUF_E * 2)             // 122880 bytes
#define NCHUNK  (CD / 32)                    // 24

template <int MODE>
__global__ __launch_bounds__(256)
void tc_gemm_kernel(const __nv_bfloat16* __restrict__ Ah,
                    const __nv_bfloat16* __restrict__ Al,
                    const __nv_bfloat16* __restrict__ Bh,
                    const __nv_bfloat16* __restrict__ Bl,
                    float* __restrict__ Cout,
                    const float* __restrict__ bias) {
    extern __shared__ __nv_bfloat16 gsm[];
    const uint32_t sbase = smem_u32(gsm);

    const int t    = threadIdx.x;
    const int wid  = t >> 5;
    const int lane = t & 31;
    const int bm   = blockIdx.y * 128;
    const int bn   = blockIdx.x * 256;

    const int warp_m = wid & 1;          // 0..1 (64-row halves)
    const int warp_n = wid >> 1;         // 0..3 (64-col quarters)
    const int r   = lane >> 2;
    const int c2  = (lane & 3) * 2;

    auto load_tiles = [&](int c, int buf) {
        const int k0 = c * 32;
        const uint32_t bofs = (uint32_t)(buf * GBUF_E) * 2;
        // A tiles: 128 rows x 32 cols, 512 chunks each (hi, lo)
#pragma unroll
        for (int i = 0; i < 2; i++) {
            const int idx = t + 256 * i;
            const int row = idx >> 2;
            const int ch  = idx & 3;
            const uint32_t so = (uint32_t)(row * TSTRIDE + ch * 8) * 2;
            const size_t g = (size_t)(bm + row) * CD + k0 + ch * 8;
            cp16(sbase + bofs + so, &Ah[g]);
            cp16(sbase + bofs + (uint32_t)GT_A * 2 + so, &Al[g]);
        }
        // B tiles: 256 rows x 32 cols, 1024 chunks each (hi, lo)
#pragma unroll
        for (int i = 0; i < 4; i++) {
            const int idx = t + 256 * i;
            const int row = idx >> 2;
            const int ch  = idx & 3;
            const uint32_t so = (uint32_t)(row * TSTRIDE + ch * 8) * 2;
            const size_t g = (size_t)(bn + row) * CD + k0 + ch * 8;
            cp16(sbase + bofs + (uint32_t)(2 * GT_A) * 2 + so, &Bh[g]);
            cp16(sbase + bofs + (uint32_t)(2 * GT_A + GT_B) * 2 + so, &Bl[g]);
        }
    };

    float acc[4][8][4];
#pragma unroll
    for (int f = 0; f < 4; f++)
#pragma unroll
        for (int g = 0; g < 8; g++)
#pragma unroll
            for (int u = 0; u < 4; u++) acc[f][g][u] = 0.0f;

    load_tiles(0, 0);
    CP_COMMIT();

    for (int c = 0; c < NCHUNK; c++) {
        const int cb = c & 1;
        if (c + 1 < NCHUNK) {
            load_tiles(c + 1, cb ^ 1);
            CP_COMMIT();
            cp_wait<1>();
        } else {
            cp_wait<0>();
        }
        __syncthreads();

        const __nv_bfloat16* AsH = gsm + cb * GBUF_E;
        const __nv_bfloat16* AsL = AsH + GT_A;
        const __nv_bfloat16* BsH = AsH + 2 * GT_A;
        const __nv_bfloat16* BsL = AsH + 2 * GT_A + GT_B;

#pragma unroll
        for (int s = 0; s < 2; s++) {
            const int kb = s * 16;
            uint32_t aH[4][4], aL[4][4];
#pragma unroll
            for (int f = 0; f < 4; f++) {
                const int m0 = warp_m * 64 + f * 16 + r;
                aH[f][0] = *(const uint32_t*)&AsH[m0 * TSTRIDE + kb + c2];
                aH[f][1] = *(const uint32_t*)&AsH[(m0 + 8) * TSTRIDE + kb + c2];
                aH[f][2] = *(const uint32_t*)&AsH[m0 * TSTRIDE + kb + 8 + c2];
                aH[f][3] = *(const uint32_t*)&AsH[(m0 + 8) * TSTRIDE + kb + 8 + c2];
                aL[f][0] = *(const uint32_t*)&AsL[m0 * TSTRIDE + kb + c2];
                aL[f][1] = *(const uint32_t*)&AsL[(m0 + 8) * TSTRIDE + kb + c2];
                aL[f][2] = *(const uint32_t*)&AsL[m0 * TSTRIDE + kb + 8 + c2];
                aL[f][3] = *(const uint32_t*)&AsL[(m0 + 8) * TSTRIDE + kb + 8 + c2];
            }
#pragma unroll
            for (int g = 0; g < 8; g++) {
                const int n0 = warp_n * 64 + g * 8 + r;
                uint32_t bH2[2], bL2[2];
                bH2[0] = *(const uint32_t*)&BsH[n0 * TSTRIDE + kb + c2];
                bH2[1] = *(const uint32_t*)&BsH[n0 * TSTRIDE + kb + 8 + c2];
                bL2[0] = *(const uint32_t*)&BsL[n0 * TSTRIDE + kb + c2];
                bL2[1] = *(const uint32_t*)&BsL[n0 * TSTRIDE + kb + 8 + c2];
#pragma unroll
                for (int f = 0; f < 4; f++) {
                    mma16816(acc[f][g], aH[f], bH2);
                    mma16816(acc[f][g], aH[f], bL2);
                    mma16816(acc[f][g], aL[f], bH2);
                }
            }
        }
        __syncthreads();
    }

#pragma unroll
    for (int f = 0; f < 4; f++) {
        const int gm0 = bm + warp_m * 64 + f * 16 + r;
#pragma unroll
        for (int g = 0; g < 8; g++) {
            const int gc = bn + warp_n * 64 + g * 8 + c2;
            if (MODE == 0) {
                const int s = gc / CD;
                const int h = (gc % CD) / HD;
                const int d = gc % HD;
                __nv_bfloat16* dsth = (s == 0) ? g_qh : (s == 1) ? g_kh : g_vh;
                __nv_bfloat16* dstl = (s == 0) ? g_ql : (s == 1) ? g_kl : g_vl;
#pragma unroll
                for (int hrow = 0; hrow < 2; hrow++) {
                    const int gm = gm0 + hrow * 8;
                    const int b  = gm >> 10;
                    const int n  = gm & 1023;
                    uint32_t hv, lv;
                    split2(acc[f][g][hrow * 2], acc[f][g][hrow * 2 + 1], hv, lv);
                    const size_t idx =
                        ((size_t)(b * NH + h) * SEQ + n) * HD + d;
                    *(uint32_t*)&dsth[idx] = hv;
                    *(uint32_t*)&dstl[idx] = lv;
                }
            } else {
                const float b0 = bias[gc], b1 = bias[gc + 1];
#pragma unroll
                for (int hrow = 0; hrow < 2; hrow++) {
                    const int gm = gm0 + hrow * 8;
                    float2 o = make_float2(acc[f][g][hrow * 2] + b0,
                                           acc[f][g][hrow * 2 + 1] + b1);
                    *(float2*)&Cout[(size_t)gm * CD + gc] = o;
                }
            }
        }
    }
}

// ---------------------------------------------------------------------------
// Quad2 attention, R15: warp tile 32 Q-rows x 128 kv (CTA = 256 Q rows),
// fused per-16kv: S block (16 regs) -> transform -> P -> PV immediately.
// Q fragments register-resident (loaded once via staging tile).
// K frag redundancy halved, V ldmatrix shared across both row-frags.
// ---------------------------------------------------------------------------
#define ATSTRIDE  72
#define AT_TILE_E (128 * ATSTRIDE)            // 9216
#define AT_KVBUF  (4 * AT_TILE_E)             // Kh,Kl,Vh,Vl
#define AT_SMEM_B ((AT_TILE_E + 2 * AT_KVBUF) * 2)   // 165888 bytes

__global__ __launch_bounds__(256)
void attn_mma_kernel() {
    extern __shared__ __nv_bfloat16 sm[];
    __nv_bfloat16* sStage = sm;                  // 128-row Q staging
    __nv_bfloat16* kv0 = sm + AT_TILE_E;
    const uint32_t kv_u32 = smem_u32(kv0);

    const int bh = blockIdx.y;
    const int r0 = blockIdx.x * 256;
    const size_t hb = (size_t)bh * SEQ * HD;

    const int t    = threadIdx.x;
    const int wid  = t >> 5;
    const int lane = t & 31;
    const int r    = lane >> 2;
    const int c2   = (lane & 3) * 2;

    // ---- Q fragment preload: warp w owns rows wid*32 .. wid*32+31 ----
    uint32_t qh[2][4][4], ql[2][4][4];
#pragma unroll
    for (int half = 0; half < 2; half++) {
#pragma unroll
        for (int src = 0; src < 2; src++) {
            const __nv_bfloat16* gq = src ? g_ql : g_qh;
            __syncthreads();                 // protect prior stage reads
#pragma unroll
            for (int i = 0; i < 4; i++) {
                const int idx = t + 256 * i;
                const int row = idx >> 3;
                const int ch  = idx & 7;
                *(uint4*)&sStage[row * ATSTRIDE + ch * 8] =
                    *(const uint4*)&gq[hb +
                        (size_t)(r0 + half * 128 + row) * HD + ch * 8];
            }
            __syncthreads();
            if ((wid >> 2) == half) {
                const int lr = (wid & 3) * 32;
#pragma unroll
                for (int f = 0; f < 2; f++) {
                    const int m0 = lr + f * 16 + r;
#pragma unroll
                    for (int dk = 0; dk < 4; dk++) {
                        const int kb = dk * 16;
                        uint32_t v0 = *(const uint32_t*)&sStage[m0 * ATSTRIDE + kb + c2];
                        uint32_t v1 = *(const uint32_t*)&sStage[(m0 + 8) * ATSTRIDE + kb + c2];
                        uint32_t v2 = *(const uint32_t*)&sStage[m0 * ATSTRIDE + kb + 8 + c2];
                        uint32_t v3 = *(const uint32_t*)&sStage[(m0 + 8) * ATSTRIDE + kb + 8 + c2];
                        if (src) { ql[f][dk][0] = v0; ql[f][dk][1] = v1;
                                   ql[f][dk][2] = v2; ql[f][dk][3] = v3; }
                        else     { qh[f][dk][0] = v0; qh[f][dk][1] = v1;
                                   qh[f][dk][2] = v2; qh[f][dk][3] = v3; }
                    }
                }
            }
        }
    }

    const __nv_bfloat16* kvsrc[4];
    kvsrc[0] = g_kh; kvsrc[1] = g_kl; kvsrc[2] = g_vh; kvsrc[3] = g_vl;

    auto load_kv = [&](int m0, int buf) {
        const uint32_t bofs = (uint32_t)(buf * AT_KVBUF) * 2;
#pragma unroll
        for (int i = 0; i < 4; i++) {
            const int idx = t + 256 * i;
            const int row = idx >> 3;
            const int ch  = idx & 7;
            const size_t g = hb + (size_t)(m0 + row) * HD + ch * 8;
            const uint32_t so = (uint32_t)(row * ATSTRIDE + ch * 8) * 2;
#pragma unroll
            for (int tt = 0; tt < 4; tt++)
                cp16(kv_u32 + bofs + (uint32_t)(tt * AT_TILE_E) * 2 + so,
                     &kvsrc[tt][g]);
        }
    };

    float O[2][8][4];
#pragma unroll
    for (int f = 0; f < 2; f++)
#pragma unroll
        for (int p = 0; p < 8; p++)
#pragma unroll
            for (int u = 0; u < 4; u++) O[f][p][u] = 0.0f;
    float den[2]  = {0.f, 0.f};
    float den8[2] = {0.f, 0.f};

    const int ld_row = (lane & 7) + 8 * ((lane >> 3) & 1);
    const int ld_col = 8 * (lane >> 4);

    load_kv(0, 0);
    CP_COMMIT();

    for (int it = 0; it < SEQ / 128; it++) {
        const int kb_ = it & 1;
        if (it + 1 < SEQ / 128) {
            load_kv((it + 1) * 128, kb_ ^ 1);
            CP_COMMIT();
            cp_wait<1>();
        } else {
            cp_wait<0>();
        }
        __syncthreads();

        const __nv_bfloat16* sKh = kv0 + kb_ * AT_KVBUF;
        const __nv_bfloat16* sKl = sKh + AT_TILE_E;
        const uint32_t vh_base = kv_u32 +
            (uint32_t)(kb_ * AT_KVBUF + 2 * AT_TILE_E) * 2;
        const uint32_t vl_base = vh_base + (uint32_t)AT_TILE_E * 2;

#pragma unroll
        for (int ks = 0; ks < 8; ks++) {
            // ---- S block: 32 Q rows x 16 kv cols, contraction dk=64 ----
            float S[2][2][4];
#pragma unroll
            for (int f = 0; f < 2; f++)
#pragma unroll
                for (int jj = 0; jj < 2; jj++)
#pragma unroll
                    for (int u = 0; u < 4; u++) S[f][jj][u] = 0.0f;

#pragma unroll
            for (int dk = 0; dk < 4; dk++) {
                const int kb = dk * 16;
#pragma unroll
                for (int jj = 0; jj < 2; jj++) {
                    const int n0 = ks * 16 + jj * 8 + r;
                    uint32_t bh2[2], bl2[2];
                    bh2[0] = *(const uint32_t*)&sKh[n0 * ATSTRIDE + kb + c2];
                    bh2[1] = *(const uint32_t*)&sKh[n0 * ATSTRIDE + kb + 8 + c2];
                    bl2[0] = *(const uint32_t*)&sKl[n0 * ATSTRIDE + kb + c2];
                    bl2[1] = *(const uint32_t*)&sKl[n0 * ATSTRIDE + kb + 8 + c2];
#pragma unroll
                    for (int f = 0; f < 2; f++) {
                        mma16816(S[f][jj], qh[f][dk], bh2);
                        mma16816(S[f][jj], qh[f][dk], bl2);
                        mma16816(S[f][jj], ql[f][dk], bh2);
                    }
                }
            }

            // ---- quad2 transform + P repack (same mapping as R12/R14) ----
            uint32_t pH[2][4], pL[2][4];
#pragma unroll
            for (int f = 0; f < 2; f++) {
                float tv[8];
#pragma unroll
                for (int u = 0; u < 4; u++) {
                    float s0 = S[f][0][u] * SCALE + QUADC;
                    float s1 = S[f][1][u] * SCALE + QUADC;
                    tv[u]     = s0 * s0;
                    tv[4 + u] = s1 * s1;
                }
                den[f]  += tv[0] + tv[1] + tv[4] + tv[5];
                den8[f] += tv[2] + tv[3] + tv[6] + tv[7];
                split2(tv[0], tv[1], pH[f][0], pL[f][0]);
                split2(tv[2], tv[3], pH[f][1], pL[f][1]);
                split2(tv[4], tv[5], pH[f][2], pL[f][2]);
                split2(tv[6], tv[7], pH[f][3], pL[f][3]);
            }

            // ---- PV: V ldmatrix shared across both f ----
            const uint32_t lofs =
                (uint32_t)(((ks * 16 + ld_row) * ATSTRIDE + ld_col) * 2);
#pragma unroll
            for (int p = 0; p < 4; p++) {
                uint32_t vh4[4], vl4[4];
                ldmx4t(vh4, vh_base + lofs + p * 32);
                ldmx4t(vl4, vl_base + lofs + p * 32);
#pragma unroll
                for (int f = 0; f < 2; f++) {
                    mma16816(O[f][2 * p],     pH[f], &vh4[0]);
                    mma16816(O[f][2 * p],     pH[f], &vl4[0]);
                    mma16816(O[f][2 * p],     pL[f], &vh4[0]);
                    mma16816(O[f][2 * p + 1], pH[f], &vh4[2]);
                    mma16816(O[f][2 * p + 1], pH[f], &vl4[2]);
                    mma16816(O[f][2 * p + 1], pL[f], &vh4[2]);
                }
            }
        }
        __syncthreads();
    }

    // ---- den quad-reduce + epilogue ----
    const int b = bh / NH;
    const int h = bh % NH;
#pragma unroll
    for (int f = 0; f < 2; f++) {
        float d0s = den[f];
        d0s += __shfl_xor_sync(0xffffffffu, d0s, 1);
        d0s += __shfl_xor_sync(0xffffffffu, d0s, 2);
        float d8s = den8[f];
        d8s += __shfl_xor_sync(0xffffffffu, d8s, 1);
        d8s += __shfl_xor_sync(0xffffffffu, d8s, 2);
        const float inv0 = 1.0f / d0s;
        const float inv1 = 1.0f / d8s;

        const int row0 = r0 + wid * 32 + f * 16 + r;
        const size_t base0 = ((size_t)(b * SEQ + row0))     * CD + h * HD;
        const size_t base1 = ((size_t)(b * SEQ + row0 + 8)) * CD + h * HD;
#pragma unroll
        for (int p = 0; p < 8; p++) {
            const int d0 = p * 8 + c2;
            uint32_t h0, l0, h1, l1;
            split2(O[f][p][0] * inv0, O[f][p][1] * inv0, h0, l0);
            split2(O[f][p][2] * inv1, O[f][p][3] * inv1, h1, l1);
            *(uint32_t*)&g_ath[base0 + d0] = h0;
            *(uint32_t*)&g_atl[base0 + d0] = l0;
            *(uint32_t*)&g_ath[base1 + d0] = h1;
            *(uint32_t*)&g_atl[base1 + d0] = l1;
        }
    }
}

// ---------------------------------------------------------------------------
extern "C" void kernel_launch(void* const* d_in, const int* in_sizes, int n_in,
                              void* d_out, int out_size) {
    const float* x = nullptr;
    const float* qkv_w = nullptr;
    const float* proj_w = nullptr;
    const float* proj_b = nullptr;
    for (int i = 0; i < n_in; i++) {
        switch (in_sizes[i]) {
            case MTOT * CD: x      = (const float*)d_in[i]; break;
            case QKVN * CD: qkv_w  = (const float*)d_in[i]; break;
            case CD * CD:   proj_w = (const float*)d_in[i]; break;
            case CD:        proj_b = (const float*)d_in[i]; break;
            default: break;
        }
    }
    float* out = (float*)d_out;

    // Device addresses of __device__ symbols (host shadow addr = R4 trap)
    __nv_bfloat16 *xh, *xl, *wh, *wl, *ph, *pl, *ath, *atl;
    cudaGetSymbolAddress((void**)&xh,  g_xh);
    cudaGetSymbolAddress((void**)&xl,  g_xl);
    cudaGetSymbolAddress((void**)&wh,  g_wh);
    cudaGetSymbolAddress((void**)&wl,  g_wl);
    cudaGetSymbolAddress((void**)&ph,  g_ph);
    cudaGetSymbolAddress((void**)&pl,  g_pl);
    cudaGetSymbolAddress((void**)&ath, g_ath);
    cudaGetSymbolAddress((void**)&atl, g_atl);

    cudaFuncSetAttribute(tc_gemm_kernel<0>,
                         cudaFuncAttributeMaxDynamicSharedMemorySize, GS_B);
    cudaFuncSetAttribute(tc_gemm_kernel<1>,
                         cudaFuncAttributeMaxDynamicSharedMemorySize, GS_B);
    cudaFuncSetAttribute(attn_mma_kernel,
                         cudaFuncAttributeMaxDynamicSharedMemorySize, AT_SMEM_B);

    // 0) split fp32 inputs into bf16 hi/lo
    split_kernel<<<(MTOT * CD) / (256 * 4), 256>>>(x, xh, xl, MTOT * CD);
    split_kernel<<<(QKVN * CD) / (256 * 4), 256>>>(qkv_w, wh, wl, QKVN * CD);
    split_kernel<<<(CD * CD)   / (256 * 4), 256>>>(proj_w, ph, pl, CD * CD);

    // 1) qkv projection -> bf16 hi/lo q/k/v   (grid: 2304/256 x 8192/128)
    tc_gemm_kernel<0><<<dim3(QKVN / 256, MTOT / 128), 256, GS_B>>>(
        xh, xl, wh, wl, nullptr, nullptr);

    // 2) quad2 attention -> g_ath/g_atl       (grid: 1024/256 x 96)
    attn_mma_kernel<<<dim3(SEQ / 256, BB * NH), 256, AT_SMEM_B>>>();

    // 3) output projection + bias             (grid: 768/256 x 8192/128)
    tc_gemm_kernel<1><<<dim3(CD / 256, MTOT / 128), 256, GS_B>>>(
        ath, atl, ph, pl, out, proj_b);
}